// round 5
// baseline (speedup 1.0000x reference)
#include <cuda_runtime.h>

// Problem constants (fixed by the dataset)
#define BN    131072            // B*N
#define TT    12
#define HH    64
#define G3    192               // 3*H
#define CC    10
#define TOUT  12
#define NT    256               // threads per block (main kernel)

// ---- shared layout (floats) ----
#define OFF_W     0             // whh^T staged k-major [k*192 + g], 12288 floats
#define OFF_WA    12288         // w_ih feature0 [192]
#define OFF_WB    12480         // w_ih feature1 [192]
#define OFF_BRZ   12672         // b_ih+b_hh for r,z gates [128]
#define OFF_BIHN  12800         // b_ih for n gates [64]
#define OFF_BHHN  12864         // b_hh for n gates [64]
#define OFF_L1W   12928         // [64]
#define OFF_L1B   12992         // [1]
#define OFF_HS    12996         // h state: float2[64][NT]  (even index -> 8B aligned)
#define SMEM_FLOATS (OFF_HS + HH*NT*2)
#define SMEM_BYTES  (SMEM_FLOATS*4)

// device-global scratch
__device__ float g_hv[(size_t)CC * TOUT * BN * 2];   // encoder inputs (x0,x1) pairs
__device__ float g_vals[(size_t)CC * TOUT * BN];     // decoder outputs

// packed f32x2 FMA (sm_103a FFMA2)
#define FMA2(acc, a, b) asm("fma.rn.f32x2 %0, %1, %2, %0;" : "+l"(acc) : "l"(a), "l"(b))

__device__ __forceinline__ unsigned long long pack2(float lo, float hi) {
    unsigned long long v;
    asm("mov.b64 %0, {%1, %2};" : "=l"(v) : "f"(lo), "f"(hi));
    return v;
}
__device__ __forceinline__ unsigned long long dup2(float x) {
    unsigned long long v;
    asm("mov.b64 %0, {%1, %1};" : "=l"(v) : "f"(x));
    return v;
}
__device__ __forceinline__ float2 unpack2(unsigned long long v) {
    float2 r;
    asm("mov.b64 {%0, %1}, %2;" : "=f"(r.x), "=f"(r.y) : "l"(v));
    return r;
}

// sigmoid via single-MUFU tanh.approx: sigma(x) = 0.5 + 0.5*tanh(x/2)
__device__ __forceinline__ float sigmoid_fast(float x) {
    float t;
    float y = 0.5f * x;
    asm("tanh.approx.f32 %0, %1;" : "=f"(t) : "f"(y));
    return fmaf(0.5f, t, 0.5f);
}
// n gate: direct single-MUFU tanh
__device__ __forceinline__ float tanh_fast(float x) {
    float t;
    asm("tanh.approx.f32 %0, %1;" : "=f"(t) : "f"(x));
    return t;
}

// One GRU step for TWO sequences (a,b) per thread, software-pipelined over
// 16 j-blocks of 4 gates: epilogue(j-4) (MUFU-heavy) is interleaved by the
// scheduler with kloop(j) (FFMA2-heavy) inside one basic block, so the MUFU
// window no longer starves the fma pipe.
// ha/hb: register-resident old h. hs (smem float2[64][NT]): holds old h at
// entry, epilogue writes new h, reload at end.
template<bool HASX1>
__device__ __forceinline__ void gru_step2(
    float (&ha)[HH], float (&hb)[HH], float* sm, int tid,
    float xa0, float xa1, float xb0, float xb1)
{
    const float* whh  = sm + OFF_W;
    float2* hs        = (float2*)(sm + OFF_HS);
    const float* wAn  = sm + OFF_WA + 128;
    const float* wBn  = sm + OFF_WB + 128;
    const float* bihn = sm + OFF_BIHN;

    unsigned long long aRa[2], aRb[2], aZa[2], aZb[2], aNa[2], aNb[2];  // current
    unsigned long long pRa[2], pRb[2], pZa[2], pZb[2], pNa[2], pNb[2];  // previous

    // ---- stage coefficients + init accumulators for block at gate offset j ----
    auto loadinit = [&](int j) {
        float wAr[4], wAz[4], wBr[4], wBz[4], bR[4], bZ[4], bN[4];
        *(float4*)wAr = *(const float4*)(sm + OFF_WA + j);
        *(float4*)wAz = *(const float4*)(sm + OFF_WA + 64 + j);
        if (HASX1) {
            *(float4*)wBr = *(const float4*)(sm + OFF_WB + j);
            *(float4*)wBz = *(const float4*)(sm + OFF_WB + 64 + j);
        }
        *(float4*)bR = *(const float4*)(sm + OFF_BRZ + j);
        *(float4*)bZ = *(const float4*)(sm + OFF_BRZ + 64 + j);
        *(float4*)bN = *(const float4*)(sm + OFF_BHHN + j);
        #pragma unroll
        for (int p = 0; p < 2; ++p) {
            int g0 = 2 * p, g1 = g0 + 1;
            float ra0 = fmaf(wAr[g0], xa0, bR[g0]);
            float ra1 = fmaf(wAr[g1], xa0, bR[g1]);
            float za0 = fmaf(wAz[g0], xa0, bZ[g0]);
            float za1 = fmaf(wAz[g1], xa0, bZ[g1]);
            float rb0 = fmaf(wAr[g0], xb0, bR[g0]);
            float rb1 = fmaf(wAr[g1], xb0, bR[g1]);
            float zb0 = fmaf(wAz[g0], xb0, bZ[g0]);
            float zb1 = fmaf(wAz[g1], xb0, bZ[g1]);
            if (HASX1) {
                ra0 = fmaf(wBr[g0], xa1, ra0); ra1 = fmaf(wBr[g1], xa1, ra1);
                za0 = fmaf(wBz[g0], xa1, za0); za1 = fmaf(wBz[g1], xa1, za1);
                rb0 = fmaf(wBr[g0], xb1, rb0); rb1 = fmaf(wBr[g1], xb1, rb1);
                zb0 = fmaf(wBz[g0], xb1, zb0); zb1 = fmaf(wBz[g1], xb1, zb1);
            }
            aRa[p] = pack2(ra0, ra1); aZa[p] = pack2(za0, za1);
            aRb[p] = pack2(rb0, rb1); aZb[p] = pack2(zb0, zb1);
            aNa[p] = pack2(bN[g0], bN[g1]);
            aNb[p] = pack2(bN[g0], bN[g1]);
        }
    };

    // ---- hh-GEMV for 4 gates: 3 LDS.128 reused across both sequences ----
    auto kloop = [&](int j) {
        const float* wb = whh + j;
        #pragma unroll
        for (int k = 0; k < HH; ++k) {
            unsigned long long ha2 = dup2(ha[k]);
            unsigned long long hb2 = dup2(hb[k]);
            ulonglong2 r = *(const ulonglong2*)(wb + k * G3);
            ulonglong2 z = *(const ulonglong2*)(wb + k * G3 + 64);
            ulonglong2 n = *(const ulonglong2*)(wb + k * G3 + 128);
            FMA2(aRa[0], ha2, r.x); FMA2(aRa[1], ha2, r.y);
            FMA2(aRb[0], hb2, r.x); FMA2(aRb[1], hb2, r.y);
            FMA2(aZa[0], ha2, z.x); FMA2(aZa[1], ha2, z.y);
            FMA2(aZb[0], hb2, z.x); FMA2(aZb[1], hb2, z.y);
            FMA2(aNa[0], ha2, n.x); FMA2(aNa[1], ha2, n.y);
            FMA2(aNb[0], hb2, n.x); FMA2(aNb[1], hb2, n.y);
        }
    };

    // ---- activations + h update for the PREVIOUS block (gate offset pj) ----
    auto epilogue = [&](int pj) {
        #pragma unroll
        for (int p = 0; p < 2; ++p) {
            float2 rva = unpack2(pRa[p]), zva = unpack2(pZa[p]), nva = unpack2(pNa[p]);
            float2 rvb = unpack2(pRb[p]), zvb = unpack2(pZb[p]), nvb = unpack2(pNb[p]);
            #pragma unroll
            for (int u = 0; u < 2; ++u) {
                int g = pj + 2 * p + u;
                float gra = u ? rva.y : rva.x, gza = u ? zva.y : zva.x, gna = u ? nva.y : nva.x;
                float grb = u ? rvb.y : rvb.x, gzb = u ? zvb.y : zvb.x, gnb = u ? nvb.y : nvb.x;
                float wan = wAn[g], bn = bihn[g];
                float gxa = fmaf(wan, xa0, bn);
                float gxb = fmaf(wan, xb0, bn);
                if (HASX1) {
                    float wbn = wBn[g];
                    gxa = fmaf(wbn, xa1, gxa);
                    gxb = fmaf(wbn, xb1, gxb);
                }
                float rsa = sigmoid_fast(gra), zsa = sigmoid_fast(gza);
                float rsb = sigmoid_fast(grb), zsb = sigmoid_fast(gzb);
                float na = tanh_fast(fmaf(rsa, gna, gxa));
                float nb = tanh_fast(fmaf(rsb, gnb, gxb));
                float2 hold = hs[g * NT + tid];
                float hna = na + zsa * (hold.x - na);
                float hnb = nb + zsb * (hold.y - nb);
                hs[g * NT + tid] = make_float2(hna, hnb);
            }
        }
    };

    auto shift = [&]() {
        #pragma unroll
        for (int i = 0; i < 2; ++i) {
            pRa[i] = aRa[i]; pRb[i] = aRb[i];
            pZa[i] = aZa[i]; pZb[i] = aZb[i];
            pNa[i] = aNa[i]; pNb[i] = aNb[i];
        }
    };

    // prologue
    loadinit(0);
    kloop(0);
    shift();

    #pragma unroll 1
    for (int j = 4; j < HH; j += 4) {
        loadinit(j);
        epilogue(j - 4);     // prev block's MUFUs interleave with kloop below
        kloop(j);
        shift();
    }
    epilogue(HH - 4);

    // reload new h into registers
    #pragma unroll
    for (int k = 0; k < HH; ++k) {
        float2 v = hs[k * NT + tid];
        ha[k] = v.x; hb[k] = v.y;
    }
}

__device__ __forceinline__ void stage_weights(
    float* sm, int tid, const float* __restrict__ whh,
    const float* __restrict__ wih, int stride,
    const float* __restrict__ bih, const float* __restrict__ bhh)
{
    for (int idx = tid; idx < G3 * HH; idx += NT) {
        int g = idx >> 6, k = idx & 63;          // global whh is [g][k]
        sm[OFF_W + k * G3 + g] = whh[idx];
    }
    if (tid < G3) {
        sm[OFF_WA + tid]  = wih[tid * stride];
        sm[OFF_WB + tid]  = (stride == 2) ? wih[tid * 2 + 1] : 0.0f;
        float bi = bih[tid], bh = bhh[tid];
        if (tid < 128) {
            sm[OFF_BRZ + tid] = bi + bh;
        } else {
            sm[OFF_BIHN + tid - 128] = bi;
            sm[OFF_BHHN + tid - 128] = bh;
        }
    }
}

__global__ void __launch_bounds__(NT, 1) krnn_main(
    const float* __restrict__ X,
    const float* __restrict__ enc_w_ih, const float* __restrict__ enc_w_hh,
    const float* __restrict__ enc_b_ih, const float* __restrict__ enc_b_hh,
    const float* __restrict__ dec_w_ih, const float* __restrict__ dec_w_hh,
    const float* __restrict__ dec_b_ih, const float* __restrict__ dec_b_hh,
    const float* __restrict__ lin1_w,   const float* __restrict__ lin1_b)
{
    extern __shared__ float sm[];
    // longest-first channel order: c=9 (24 steps) dispatched first,
    // so the tail wave runs the shortest blocks.
    const int c   = (CC - 1) - blockIdx.y;
    const int tid = threadIdx.x;

    // stage ENCODER weights
    stage_weights(sm, tid, enc_w_hh + c * (G3 * HH), enc_w_ih + c * (G3 * 2), 2,
                  enc_b_ih + c * G3, enc_b_hh + c * G3);
    __syncthreads();

    const int seqa = (blockIdx.x * NT + tid) * 2;   // this thread: seqs (seqa, seqa+1)
    float2* hs = (float2*)(sm + OFF_HS);

    // prefetch decoder seed values early (hide DRAM latency under encoder)
    float lva = X[(size_t)seqa * (TT * 2) + 22];          // X[seq, t=11, f=0]
    float lvb = X[(size_t)(seqa + 1) * (TT * 2) + 22];

    float ha[HH], hb[HH];
    #pragma unroll
    for (int k = 0; k < HH; ++k) {
        ha[k] = 0.0f; hb[k] = 0.0f;
        hs[k * NT + tid] = make_float2(0.0f, 0.0f);   // own slots only, no sync needed
    }

    // ---- encoder ----
    const int s = c + 3;
    const float2* hvp = (const float2*)g_hv;
    for (int st = 0; st < s; ++st) {
        float4 xv = *(const float4*)(hvp + (size_t)(c * TOUT + st) * BN + seqa);
        gru_step2<true>(ha, hb, sm, tid, xv.x, xv.y, xv.z, xv.w);
    }

    // restage DECODER weights over the same buffer
    __syncthreads();
    stage_weights(sm, tid, dec_w_hh + c * (G3 * HH), dec_w_ih + c * G3, 1,
                  dec_b_ih + c * G3, dec_b_hh + c * G3);
    if (tid < HH)  sm[OFF_L1W + tid] = lin1_w[c * HH + tid];
    if (tid == HH) sm[OFF_L1B] = lin1_b[c];
    __syncthreads();

    // ---- decoder ----
    const float l1b = sm[OFF_L1B];
    for (int st = 0; st < TOUT; ++st) {
        gru_step2<false>(ha, hb, sm, tid, lva, 0.0f, lvb, 0.0f);
        float va = l1b, vb = l1b;
        #pragma unroll
        for (int k = 0; k < HH; ++k) {
            float w = sm[OFF_L1W + k];
            va = fmaf(ha[k], w, va);
            vb = fmaf(hb[k], w, vb);
        }
        *(float2*)&g_vals[(size_t)(c * TOUT + st) * BN + seqa] = make_float2(va, vb);
        lva = va; lvb = vb;
    }
}

// precompute encoder inputs hv[c][st][seq] = (x0,x1)
__global__ void __launch_bounds__(256) krnn_hv(
    const float* __restrict__ X,
    const float* __restrict__ lin2_w, const float* __restrict__ lin2_b)
{
    const int seq = blockIdx.x * 256 + threadIdx.x;
    float Xl[24];
    {
        const float4* xp = (const float4*)(X + (size_t)seq * (TT * 2));
        #pragma unroll
        for (int q = 0; q < 6; ++q) {
            float4 v = xp[q];
            Xl[4*q+0] = v.x; Xl[4*q+1] = v.y; Xl[4*q+2] = v.z; Xl[4*q+3] = v.w;
        }
    }
    float2* hvp = (float2*)g_hv;
    for (int c = 0; c < CC; ++c) {
        const int s = c + 3;
        for (int st = 0; st < s; ++st) {
            float b = lin2_b[c * 12 + st];
            float x0 = b, x1 = b;
            #pragma unroll
            for (int t = 0; t < TT; ++t) {
                float w = lin2_w[c * 144 + st * 12 + t];
                x0 = fmaf(Xl[2 * t],     w, x0);
                x1 = fmaf(Xl[2 * t + 1], w, x1);
            }
            hvp[(size_t)(c * TOUT + st) * BN + seq] = make_float2(x0, x1);
        }
    }
}

__global__ void __launch_bounds__(256) krnn_combine(
    const float* __restrict__ X,
    const float* __restrict__ embed1,
    float* __restrict__ out)
{
    const int seq = blockIdx.x * 256 + threadIdx.x;

    float q[TT];
    #pragma unroll
    for (int t = 0; t < TT; ++t) q[t] = X[(size_t)seq * (TT * 2) + t * 2];

    float wq[TOUT];
    #pragma unroll
    for (int o = 0; o < TOUT; ++o) {
        float a = 0.0f;
        #pragma unroll
        for (int t = 0; t < TT; ++t) a = fmaf(q[t], embed1[t * TOUT + o], a);
        wq[o] = a;
    }

    float ov[TOUT * CC];
    #pragma unroll
    for (int cc = 0; cc < CC; ++cc)
        #pragma unroll
        for (int o = 0; o < TOUT; ++o)
            ov[o * CC + cc] = g_vals[((size_t)cc * TOUT + o) * BN + seq];

    float wc[CC];
    #pragma unroll
    for (int cc = 0; cc < CC; ++cc) {
        float a = 0.0f;
        #pragma unroll
        for (int o = 0; o < TOUT; ++o) a = fmaf(wq[o], ov[o * CC + cc], a);
        wc[cc] = a;
    }

    float m = wc[0];
    #pragma unroll
    for (int cc = 1; cc < CC; ++cc) m = fmaxf(m, wc[cc]);
    float e[CC]; float ssum = 0.0f;
    #pragma unroll
    for (int cc = 0; cc < CC; ++cc) { e[cc] = expf(wc[cc] - m); ssum += e[cc]; }
    float inv = 1.0f / ssum;

    #pragma unroll
    for (int o = 0; o < TOUT; ++o) {
        float a = 0.0f;
        #pragma unroll
        for (int cc = 0; cc < CC; ++cc) a = fmaf(ov[o * CC + cc], e[cc], a);
        out[(size_t)seq * TOUT + o] = a * inv;
    }
}

extern "C" void kernel_launch(void* const* d_in, const int* in_sizes, int n_in,
                              void* d_out, int out_size)
{
    // input order: A, X, enc_w_ih, enc_w_hh, enc_b_ih, enc_b_hh,
    //              dec_w_ih, dec_w_hh, dec_b_ih, dec_b_hh,
    //              lin1_w, lin1_b, lin2_w, lin2_b, embed1
    const float* X        = (const float*)d_in[1];
    const float* enc_w_ih = (const float*)d_in[2];
    const float* enc_w_hh = (const float*)d_in[3];
    const float* enc_b_ih = (const float*)d_in[4];
    const float* enc_b_hh = (const float*)d_in[5];
    const float* dec_w_ih = (const float*)d_in[6];
    const float* dec_w_hh = (const float*)d_in[7];
    const float* dec_b_ih = (const float*)d_in[8];
    const float* dec_b_hh = (const float*)d_in[9];
    const float* lin1_w   = (const float*)d_in[10];
    const float* lin1_b   = (const float*)d_in[11];
    const float* lin2_w   = (const float*)d_in[12];
    const float* lin2_b   = (const float*)d_in[13];
    const float* embed1   = (const float*)d_in[14];

    cudaFuncSetAttribute(krnn_main, cudaFuncAttributeMaxDynamicSharedMemorySize, SMEM_BYTES);

    krnn_hv<<<BN / 256, 256>>>(X, lin2_w, lin2_b);

    dim3 grid(BN / (NT * 2), CC);
    krnn_main<<<grid, NT, SMEM_BYTES>>>(
        X, enc_w_ih, enc_w_hh, enc_b_ih, enc_b_hh,
        dec_w_ih, dec_w_hh, dec_b_ih, dec_b_hh,
        lin1_w, lin1_b);

    krnn_combine<<<BN / 256, 256>>>(X, embed1, (float*)d_out);
}

// round 6
// speedup vs baseline: 1.1817x; 1.1817x over previous
#include <cuda_runtime.h>

// Problem constants (fixed by the dataset)
#define BN    131072            // B*N
#define TT    12
#define HH    64
#define G3    192               // 3*H
#define CC    10
#define TOUT  12
#define NT    256               // threads per block (main kernel)

// ---- shared layout (floats) ----
#define OFF_W     0             // whh^T staged k-major [k*192 + g], 12288 floats
#define OFF_WA    12288         // w_ih feature0 [192]
#define OFF_WB    12480         // w_ih feature1 [192]
#define OFF_BRZ   12672         // b_ih+b_hh for r,z gates [128]
#define OFF_BIHN  12800         // b_ih for n gates [64]
#define OFF_BHHN  12864         // b_hh for n gates [64]
#define OFF_L1W   12928         // [64]
#define OFF_L1B   12992         // [1]
#define OFF_HS    12996         // h state: float2[64][NT]  (even index -> 8B aligned)
#define SMEM_FLOATS (OFF_HS + HH*NT*2)
#define SMEM_BYTES  (SMEM_FLOATS*4)

// device-global scratch
__device__ float g_hv[(size_t)CC * TOUT * BN * 2];   // encoder inputs (x0,x1) pairs
__device__ float g_vals[(size_t)CC * TOUT * BN];     // decoder outputs

// packed f32x2 FMA (sm_103a FFMA2)
#define FMA2(acc, a, b) asm("fma.rn.f32x2 %0, %1, %2, %0;" : "+l"(acc) : "l"(a), "l"(b))

__device__ __forceinline__ unsigned long long pack2(float lo, float hi) {
    unsigned long long v;
    asm("mov.b64 %0, {%1, %2};" : "=l"(v) : "f"(lo), "f"(hi));
    return v;
}
__device__ __forceinline__ unsigned long long dup2(float x) {
    unsigned long long v;
    asm("mov.b64 %0, {%1, %1};" : "=l"(v) : "f"(x));
    return v;
}
__device__ __forceinline__ float2 unpack2(unsigned long long v) {
    float2 r;
    asm("mov.b64 {%0, %1}, %2;" : "=f"(r.x), "=f"(r.y) : "l"(v));
    return r;
}

// sigmoid via single-MUFU tanh.approx: sigma(x) = 0.5 + 0.5*tanh(x/2)
__device__ __forceinline__ float sigmoid_fast(float x) {
    float t;
    float y = 0.5f * x;
    asm("tanh.approx.f32 %0, %1;" : "=f"(t) : "f"(y));
    return fmaf(0.5f, t, 0.5f);
}
// n gate: direct single-MUFU tanh
__device__ __forceinline__ float tanh_fast(float x) {
    float t;
    asm("tanh.approx.f32 %0, %1;" : "=f"(t) : "f"(x));
    return t;
}

// One GRU step for TWO sequences (a,b) per thread.
// ha/hb: register-resident old h. hs (smem float2[64][NT]): holds old h at entry
// (invariant maintained by previous step's epilogue), epilogue writes new h,
// reload at end. wrot: per-warp j-block rotation.
// j-loop unrolled by 2: a pair of blocks forms one straight-line region so
// ptxas can schedule block-i's MUFU-heavy epilogue into block-(i+1)'s
// FFMA2-heavy kloop (fills the fma pipe during the MUFU window).
template<bool HASX1>
__device__ __forceinline__ void gru_step2(
    float (&ha)[HH], float (&hb)[HH], float* sm, int tid, int wrot,
    float xa0, float xa1, float xb0, float xb1)
{
    const float* whh = sm + OFF_W;
    float2* hs = (float2*)(sm + OFF_HS);

    #pragma unroll 2
    for (int jb = 0; jb < 8; ++jb) {
        const int j = ((jb + wrot) & 7) << 3;

        // ---- stage per-block coefficients (vectorized shared loads) ----
        float wAr[8], wAz[8], wBr[8], wBz[8], bR[8], bZ[8], bN[8];
        *(float4*)(wAr)     = *(const float4*)(sm + OFF_WA + j);
        *(float4*)(wAr + 4) = *(const float4*)(sm + OFF_WA + j + 4);
        *(float4*)(wAz)     = *(const float4*)(sm + OFF_WA + 64 + j);
        *(float4*)(wAz + 4) = *(const float4*)(sm + OFF_WA + 64 + j + 4);
        if (HASX1) {
            *(float4*)(wBr)     = *(const float4*)(sm + OFF_WB + j);
            *(float4*)(wBr + 4) = *(const float4*)(sm + OFF_WB + j + 4);
            *(float4*)(wBz)     = *(const float4*)(sm + OFF_WB + 64 + j);
            *(float4*)(wBz + 4) = *(const float4*)(sm + OFF_WB + 64 + j + 4);
        }
        *(float4*)(bR)     = *(const float4*)(sm + OFF_BRZ + j);
        *(float4*)(bR + 4) = *(const float4*)(sm + OFF_BRZ + j + 4);
        *(float4*)(bZ)     = *(const float4*)(sm + OFF_BRZ + 64 + j);
        *(float4*)(bZ + 4) = *(const float4*)(sm + OFF_BRZ + 64 + j + 4);
        *(float4*)(bN)     = *(const float4*)(sm + OFF_BHHN + j);
        *(float4*)(bN + 4) = *(const float4*)(sm + OFF_BHHN + j + 4);

        // ---- accumulator init: gx(r,z)+biases ; b_hh only for n ----
        unsigned long long aRa[4], aZa[4], aNa[4], aRb[4], aZb[4], aNb[4];
        #pragma unroll
        for (int p = 0; p < 4; ++p) {
            int g0 = 2 * p, g1 = g0 + 1;
            float ra0 = fmaf(wAr[g0], xa0, bR[g0]);
            float ra1 = fmaf(wAr[g1], xa0, bR[g1]);
            float za0 = fmaf(wAz[g0], xa0, bZ[g0]);
            float za1 = fmaf(wAz[g1], xa0, bZ[g1]);
            float rb0 = fmaf(wAr[g0], xb0, bR[g0]);
            float rb1 = fmaf(wAr[g1], xb0, bR[g1]);
            float zb0 = fmaf(wAz[g0], xb0, bZ[g0]);
            float zb1 = fmaf(wAz[g1], xb0, bZ[g1]);
            if (HASX1) {
                ra0 = fmaf(wBr[g0], xa1, ra0); ra1 = fmaf(wBr[g1], xa1, ra1);
                za0 = fmaf(wBz[g0], xa1, za0); za1 = fmaf(wBz[g1], xa1, za1);
                rb0 = fmaf(wBr[g0], xb1, rb0); rb1 = fmaf(wBr[g1], xb1, rb1);
                zb0 = fmaf(wBz[g0], xb1, zb0); zb1 = fmaf(wBz[g1], xb1, zb1);
            }
            aRa[p] = pack2(ra0, ra1); aZa[p] = pack2(za0, za1);
            aRb[p] = pack2(rb0, rb1); aZb[p] = pack2(zb0, zb1);
            aNa[p] = pack2(bN[g0], bN[g1]);
            aNb[p] = pack2(bN[g0], bN[g1]);
        }

        // ---- hh-GEMV inner loop: 6 LDS.128 reused across both sequences ----
        const float* wb = whh + j;
        #pragma unroll
        for (int k = 0; k < HH; ++k) {
            unsigned long long ha2 = dup2(ha[k]);
            unsigned long long hb2 = dup2(hb[k]);
            const ulonglong2* pr = (const ulonglong2*)(wb + k * G3);
            const ulonglong2* pz = (const ulonglong2*)(wb + k * G3 + 64);
            const ulonglong2* pn = (const ulonglong2*)(wb + k * G3 + 128);
            ulonglong2 r0 = pr[0], r1 = pr[1];
            ulonglong2 z0 = pz[0], z1 = pz[1];
            ulonglong2 n0 = pn[0], n1 = pn[1];
            FMA2(aRa[0], ha2, r0.x); FMA2(aRa[1], ha2, r0.y);
            FMA2(aRa[2], ha2, r1.x); FMA2(aRa[3], ha2, r1.y);
            FMA2(aRb[0], hb2, r0.x); FMA2(aRb[1], hb2, r0.y);
            FMA2(aRb[2], hb2, r1.x); FMA2(aRb[3], hb2, r1.y);
            FMA2(aZa[0], ha2, z0.x); FMA2(aZa[1], ha2, z0.y);
            FMA2(aZa[2], ha2, z1.x); FMA2(aZa[3], ha2, z1.y);
            FMA2(aZb[0], hb2, z0.x); FMA2(aZb[1], hb2, z0.y);
            FMA2(aZb[2], hb2, z1.x); FMA2(aZb[3], hb2, z1.y);
            FMA2(aNa[0], ha2, n0.x); FMA2(aNa[1], ha2, n0.y);
            FMA2(aNa[2], ha2, n1.x); FMA2(aNa[3], ha2, n1.y);
            FMA2(aNb[0], hb2, n0.x); FMA2(aNb[1], hb2, n0.y);
            FMA2(aNb[2], hb2, n1.x); FMA2(aNb[3], hb2, n1.y);
        }

        // ---- epilogue: activations + h update (new h -> hs) ----
        const float* wAn  = sm + OFF_WA + 128;
        const float* wBn  = sm + OFF_WB + 128;
        const float* bihn = sm + OFF_BIHN;
        #pragma unroll
        for (int p = 0; p < 4; ++p) {
            float2 rva = unpack2(aRa[p]), zva = unpack2(aZa[p]), nva = unpack2(aNa[p]);
            float2 rvb = unpack2(aRb[p]), zvb = unpack2(aZb[p]), nvb = unpack2(aNb[p]);
            #pragma unroll
            for (int u = 0; u < 2; ++u) {
                int g = j + 2 * p + u;
                float gra = u ? rva.y : rva.x, gza = u ? zva.y : zva.x, gna = u ? nva.y : nva.x;
                float grb = u ? rvb.y : rvb.x, gzb = u ? zvb.y : zvb.x, gnb = u ? nvb.y : nvb.x;
                float wan = wAn[g], bn = bihn[g];
                float gxa = fmaf(wan, xa0, bn);
                float gxb = fmaf(wan, xb0, bn);
                if (HASX1) {
                    float wbn = wBn[g];
                    gxa = fmaf(wbn, xa1, gxa);
                    gxb = fmaf(wbn, xb1, gxb);
                }
                float rsa = sigmoid_fast(gra), zsa = sigmoid_fast(gza);
                float rsb = sigmoid_fast(grb), zsb = sigmoid_fast(gzb);
                float na = tanh_fast(fmaf(rsa, gna, gxa));
                float nb = tanh_fast(fmaf(rsb, gnb, gxb));
                float2 hold = hs[g * NT + tid];
                float hna = na + zsa * (hold.x - na);
                float hnb = nb + zsb * (hold.y - nb);
                hs[g * NT + tid] = make_float2(hna, hnb);
            }
        }
    }

    // reload new h into registers
    #pragma unroll
    for (int k = 0; k < HH; ++k) {
        float2 v = hs[k * NT + tid];
        ha[k] = v.x; hb[k] = v.y;
    }
}

__device__ __forceinline__ void stage_weights(
    float* sm, int tid, const float* __restrict__ whh,
    const float* __restrict__ wih, int stride,
    const float* __restrict__ bih, const float* __restrict__ bhh)
{
    for (int idx = tid; idx < G3 * HH; idx += NT) {
        int g = idx >> 6, k = idx & 63;          // global whh is [g][k]
        sm[OFF_W + k * G3 + g] = whh[idx];
    }
    if (tid < G3) {
        sm[OFF_WA + tid]  = wih[tid * stride];
        sm[OFF_WB + tid]  = (stride == 2) ? wih[tid * 2 + 1] : 0.0f;
        float bi = bih[tid], bh = bhh[tid];
        if (tid < 128) {
            sm[OFF_BRZ + tid] = bi + bh;
        } else {
            sm[OFF_BIHN + tid - 128] = bi;
            sm[OFF_BHHN + tid - 128] = bh;
        }
    }
}

__global__ void __launch_bounds__(NT, 1) krnn_main(
    const float* __restrict__ X,
    const float* __restrict__ enc_w_ih, const float* __restrict__ enc_w_hh,
    const float* __restrict__ enc_b_ih, const float* __restrict__ enc_b_hh,
    const float* __restrict__ dec_w_ih, const float* __restrict__ dec_w_hh,
    const float* __restrict__ dec_b_ih, const float* __restrict__ dec_b_hh,
    const float* __restrict__ lin1_w,   const float* __restrict__ lin1_b)
{
    extern __shared__ float sm[];
    // longest-first channel order: c=9 (24 steps) dispatched first,
    // so the tail wave runs the shortest blocks.
    const int c    = (CC - 1) - blockIdx.y;
    const int tid  = threadIdx.x;
    const int wrot = tid >> 5;     // per-warp j-block rotation (0..7)

    // stage ENCODER weights
    stage_weights(sm, tid, enc_w_hh + c * (G3 * HH), enc_w_ih + c * (G3 * 2), 2,
                  enc_b_ih + c * G3, enc_b_hh + c * G3);
    __syncthreads();

    const int seqa = (blockIdx.x * NT + tid) * 2;   // this thread: seqs (seqa, seqa+1)
    float2* hs = (float2*)(sm + OFF_HS);

    // prefetch decoder seed values early (hide DRAM latency under encoder)
    float lva = X[(size_t)seqa * (TT * 2) + 22];          // X[seq, t=11, f=0]
    float lvb = X[(size_t)(seqa + 1) * (TT * 2) + 22];

    float ha[HH], hb[HH];
    #pragma unroll
    for (int k = 0; k < HH; ++k) {
        ha[k] = 0.0f; hb[k] = 0.0f;
        hs[k * NT + tid] = make_float2(0.0f, 0.0f);   // own slots only, no sync needed
    }

    // ---- encoder ----
    const int s = c + 3;
    const float2* hvp = (const float2*)g_hv;
    for (int st = 0; st < s; ++st) {
        float4 xv = *(const float4*)(hvp + (size_t)(c * TOUT + st) * BN + seqa);
        gru_step2<true>(ha, hb, sm, tid, wrot, xv.x, xv.y, xv.z, xv.w);
    }

    // restage DECODER weights over the same buffer
    __syncthreads();
    stage_weights(sm, tid, dec_w_hh + c * (G3 * HH), dec_w_ih + c * G3, 1,
                  dec_b_ih + c * G3, dec_b_hh + c * G3);
    if (tid < HH)  sm[OFF_L1W + tid] = lin1_w[c * HH + tid];
    if (tid == HH) sm[OFF_L1B] = lin1_b[c];
    __syncthreads();

    // ---- decoder ----
    const float l1b = sm[OFF_L1B];
    for (int st = 0; st < TOUT; ++st) {
        gru_step2<false>(ha, hb, sm, tid, wrot, lva, 0.0f, lvb, 0.0f);
        float va = l1b, vb = l1b;
        #pragma unroll
        for (int k = 0; k < HH; ++k) {
            float w = sm[OFF_L1W + k];
            va = fmaf(ha[k], w, va);
            vb = fmaf(hb[k], w, vb);
        }
        *(float2*)&g_vals[(size_t)(c * TOUT + st) * BN + seqa] = make_float2(va, vb);
        lva = va; lvb = vb;
    }
}

// precompute encoder inputs hv[c][st][seq] = (x0,x1)
__global__ void __launch_bounds__(256) krnn_hv(
    const float* __restrict__ X,
    const float* __restrict__ lin2_w, const float* __restrict__ lin2_b)
{
    const int seq = blockIdx.x * 256 + threadIdx.x;
    float Xl[24];
    {
        const float4* xp = (const float4*)(X + (size_t)seq * (TT * 2));
        #pragma unroll
        for (int q = 0; q < 6; ++q) {
            float4 v = xp[q];
            Xl[4*q+0] = v.x; Xl[4*q+1] = v.y; Xl[4*q+2] = v.z; Xl[4*q+3] = v.w;
        }
    }
    float2* hvp = (float2*)g_hv;
    for (int c = 0; c < CC; ++c) {
        const int s = c + 3;
        for (int st = 0; st < s; ++st) {
            float b = lin2_b[c * 12 + st];
            float x0 = b, x1 = b;
            #pragma unroll
            for (int t = 0; t < TT; ++t) {
                float w = lin2_w[c * 144 + st * 12 + t];
                x0 = fmaf(Xl[2 * t],     w, x0);
                x1 = fmaf(Xl[2 * t + 1], w, x1);
            }
            hvp[(size_t)(c * TOUT + st) * BN + seq] = make_float2(x0, x1);
        }
    }
}

__global__ void __launch_bounds__(256) krnn_combine(
    const float* __restrict__ X,
    const float* __restrict__ embed1,
    float* __restrict__ out)
{
    const int seq = blockIdx.x * 256 + threadIdx.x;

    float q[TT];
    #pragma unroll
    for (int t = 0; t < TT; ++t) q[t] = X[(size_t)seq * (TT * 2) + t * 2];

    float wq[TOUT];
    #pragma unroll
    for (int o = 0; o < TOUT; ++o) {
        float a = 0.0f;
        #pragma unroll
        for (int t = 0; t < TT; ++t) a = fmaf(q[t], embed1[t * TOUT + o], a);
        wq[o] = a;
    }

    float ov[TOUT * CC];
    #pragma unroll
    for (int cc = 0; cc < CC; ++cc)
        #pragma unroll
        for (int o = 0; o < TOUT; ++o)
            ov[o * CC + cc] = g_vals[((size_t)cc * TOUT + o) * BN + seq];

    float wc[CC];
    #pragma unroll
    for (int cc = 0; cc < CC; ++cc) {
        float a = 0.0f;
        #pragma unroll
        for (int o = 0; o < TOUT; ++o) a = fmaf(wq[o], ov[o * CC + cc], a);
        wc[cc] = a;
    }

    float m = wc[0];
    #pragma unroll
    for (int cc = 1; cc < CC; ++cc) m = fmaxf(m, wc[cc]);
    float e[CC]; float ssum = 0.0f;
    #pragma unroll
    for (int cc = 0; cc < CC; ++cc) { e[cc] = expf(wc[cc] - m); ssum += e[cc]; }
    float inv = 1.0f / ssum;

    #pragma unroll
    for (int o = 0; o < TOUT; ++o) {
        float a = 0.0f;
        #pragma unroll
        for (int cc = 0; cc < CC; ++cc) a = fmaf(ov[o * CC + cc], e[cc], a);
        out[(size_t)seq * TOUT + o] = a * inv;
    }
}

extern "C" void kernel_launch(void* const* d_in, const int* in_sizes, int n_in,
                              void* d_out, int out_size)
{
    // input order: A, X, enc_w_ih, enc_w_hh, enc_b_ih, enc_b_hh,
    //              dec_w_ih, dec_w_hh, dec_b_ih, dec_b_hh,
    //              lin1_w, lin1_b, lin2_w, lin2_b, embed1
    const float* X        = (const float*)d_in[1];
    const float* enc_w_ih = (const float*)d_in[2];
    const float* enc_w_hh = (const float*)d_in[3];
    const float* enc_b_ih = (const float*)d_in[4];
    const float* enc_b_hh = (const float*)d_in[5];
    const float* dec_w_ih = (const float*)d_in[6];
    const float* dec_w_hh = (const float*)d_in[7];
    const float* dec_b_ih = (const float*)d_in[8];
    const float* dec_b_hh = (const float*)d_in[9];
    const float* lin1_w   = (const float*)d_in[10];
    const float* lin1_b   = (const float*)d_in[11];
    const float* lin2_w   = (const float*)d_in[12];
    const float* lin2_b   = (const float*)d_in[13];
    const float* embed1   = (const float*)d_in[14];

    cudaFuncSetAttribute(krnn_main, cudaFuncAttributeMaxDynamicSharedMemorySize, SMEM_BYTES);

    krnn_hv<<<BN / 256, 256>>>(X, lin2_w, lin2_b);

    dim3 grid(BN / (NT * 2), CC);
    krnn_main<<<grid, NT, SMEM_BYTES>>>(
        X, enc_w_ih, enc_w_hh, enc_b_ih, enc_b_hh,
        dec_w_ih, dec_w_hh, dec_b_ih, dec_b_hh,
        lin1_w, lin1_b);

    krnn_combine<<<BN / 256, 256>>>(X, embed1, (float*)d_out);
}

// round 8
// speedup vs baseline: 2.5043x; 2.1193x over previous
#include <cuda_runtime.h>
#include <cuda_bf16.h>
#include <cstdint>

// Problem constants
#define BN    131072
#define TT    12
#define HH    64
#define G3    192
#define CC    10
#define TOUT  12
#define NT    256            // 8 warps; warp = 16 seqs; CTA = 128 seqs
#define SEQ_PER_CTA 128

// ---- SMEM byte offsets ----
#define OFF_AHI  0                 // h hi: 128 rows x 128B (64 bf16), swizzled
#define OFF_ALO  16384             // h lo
#define OFF_WHI  32768             // W hi: 192 rows x 128B, swizzled
#define OFF_WLO  57344             // W lo
#define OFF_COEF 81920             // float arrays
#define CF_WA   0                  // w_ih feature0 [192]
#define CF_WB   192                // w_ih feature1 [192]
#define CF_BRZ  384                // b_ih+b_hh for r,z [128]
#define CF_BIHN 512                // b_ih n [64]
#define CF_BHHN 576                // b_hh n [64]
#define SMEM_BYTES (OFF_COEF + 640*4)

// device-global scratch
__device__ float g_hv[(size_t)CC * TOUT * BN * 2];   // encoder inputs (x0,x1)
__device__ float g_vals[(size_t)CC * TOUT * BN];     // decoder outputs

// ===================== helpers =====================
__device__ __forceinline__ uint32_t smem_u32_of(const void* p) {
    uint32_t a;
    asm("{ .reg .u64 t; cvta.to.shared.u64 t, %1; cvt.u32.u64 %0, t; }" : "=r"(a) : "l"(p));
    return a;
}
__device__ __forceinline__ float sigmoid_fast(float x) {
    float t, y = 0.5f * x;
    asm("tanh.approx.f32 %0, %1;" : "=f"(t) : "f"(y));
    return fmaf(0.5f, t, 0.5f);
}
__device__ __forceinline__ float tanh_fast(float x) {
    float t;
    asm("tanh.approx.f32 %0, %1;" : "=f"(t) : "f"(x));
    return t;
}

#define LDSM_X4(r0, r1, r2, r3, addr) \
    asm volatile("ldmatrix.sync.aligned.m8n8.x4.shared.b16 {%0,%1,%2,%3}, [%4];" \
                 : "=r"(r0), "=r"(r1), "=r"(r2), "=r"(r3) : "r"(addr))

#define MMA16816(dp, a0, a1, a2, a3, b0, b1) \
    asm volatile("mma.sync.aligned.m16n8k16.row.col.f32.bf16.bf16.f32 " \
                 "{%0,%1,%2,%3}, {%4,%5,%6,%7}, {%8,%9}, {%0,%1,%2,%3};" \
                 : "+f"((dp)[0]), "+f"((dp)[1]), "+f"((dp)[2]), "+f"((dp)[3]) \
                 : "r"(a0), "r"(a1), "r"(a2), "r"(a3), "r"(b0), "r"(b1))

// ===================== weight staging =====================
__device__ __forceinline__ void stage_w(
    unsigned char* smem, int tid,
    const float* __restrict__ whh, const float* __restrict__ wih, int stride,
    const float* __restrict__ bih, const float* __restrict__ bhh)
{
    for (int idx = tid; idx < G3 * HH; idx += NT) {
        int g = idx >> 6, k = idx & 63;
        float w = whh[idx];
        __nv_bfloat16 hi = __float2bfloat16_rn(w);
        __nv_bfloat16 lo = __float2bfloat16_rn(w - __bfloat162float(hi));
        uint32_t off = (uint32_t)g * 128u + (uint32_t)((((k >> 3) ^ (g & 7)) << 4) + (k & 7) * 2);
        *(__nv_bfloat16*)(smem + OFF_WHI + off) = hi;
        *(__nv_bfloat16*)(smem + OFF_WLO + off) = lo;
    }
    float* cf = (float*)(smem + OFF_COEF);
    for (int t = tid; t < G3; t += NT) {
        cf[CF_WA + t] = wih[t * stride];
        cf[CF_WB + t] = (stride == 2) ? wih[t * 2 + 1] : 0.0f;
        float bi = bih[t], bh = bhh[t];
        if (t < 128) cf[CF_BRZ + t] = bi + bh;
        else { cf[CF_BIHN + t - 128] = bi; cf[CF_BHHN + t - 128] = bh; }
    }
}

// ===================== one GRU step (mma.sync) =====================
// D = W·h via 12 k-steps: ks 0-3: Whi*hhi, 4-7: Whi*hlo, 8-11: Wlo*hhi.
// hreg: fp32 h in D-fragment layout (index t*4 + rh*2 + u). Epilogue writes
// new h to hreg and split-bf16 A tiles (own warp's rows only -> syncwarp only).
template<bool HASX1>
__device__ __forceinline__ void mma_step(
    unsigned char* smem, uint32_t smb, const float* cf, float* hreg,
    int warp, int group, int tg,
    int arow, int acoff, int brow, int bcoff, int sw7,
    float xa0, float xa1, float xb0, float xb1)
{
    float D[96];
    #pragma unroll
    for (int i = 0; i < 96; ++i) D[i] = 0.0f;

    __syncwarp();

    const uint32_t a_row_b = (uint32_t)(warp * 16 + arow) * 128u;

    #pragma unroll 1
    for (int ks = 0; ks < 12; ++ks) {
        const int part = ks >> 2;                      // 0,1,2
        const uint32_t abase = smb + (part == 1 ? OFF_ALO : OFF_AHI);
        const uint32_t wbase = smb + (part == 2 ? OFF_WLO : OFF_WHI);
        const int kcb = (ks & 3) * 2;

        uint32_t A0, A1, A2, A3;
        uint32_t aaddr = abase + a_row_b + (uint32_t)(((kcb + acoff) ^ sw7) << 4);
        LDSM_X4(A0, A1, A2, A3, aaddr);

        const uint32_t bsw = (uint32_t)(((kcb + bcoff) ^ sw7) << 4);
        #pragma unroll
        for (int bt = 0; bt < 12; ++bt) {
            uint32_t baddr = wbase + (uint32_t)(bt * 16 + brow) * 128u + bsw;
            uint32_t B0, B1, B2, B3;
            LDSM_X4(B0, B1, B2, B3, baddr);
            MMA16816(&D[(2 * bt) * 4],     A0, A1, A2, A3, B0, B1);
            MMA16816(&D[(2 * bt + 1) * 4], A0, A1, A2, A3, B2, B3);
        }
    }

    __syncwarp();

    // ---- epilogue: gates, h update, split-bf16 store ----
    #pragma unroll
    for (int t = 0; t < 8; ++t) {
        const int g2 = t * 8 + tg * 2;
        float2 war = *(const float2*)(cf + CF_WA + g2);
        float2 waz = *(const float2*)(cf + CF_WA + 64 + g2);
        float2 wan = *(const float2*)(cf + CF_WA + 128 + g2);
        float2 brr = *(const float2*)(cf + CF_BRZ + g2);
        float2 brz = *(const float2*)(cf + CF_BRZ + 64 + g2);
        float2 bin = *(const float2*)(cf + CF_BIHN + g2);
        float2 bhn = *(const float2*)(cf + CF_BHHN + g2);
        float2 wbr, wbz, wbn;
        if (HASX1) {
            wbr = *(const float2*)(cf + CF_WB + g2);
            wbz = *(const float2*)(cf + CF_WB + 64 + g2);
            wbn = *(const float2*)(cf + CF_WB + 128 + g2);
        }
        #pragma unroll
        for (int rh = 0; rh < 2; ++rh) {
            const float x0 = rh ? xb0 : xa0;
            const float x1 = rh ? xb1 : xa1;
            float hn[2];
            #pragma unroll
            for (int u = 0; u < 2; ++u) {
                float pr = D[t * 4 + rh * 2 + u]        + (u ? brr.y : brr.x) + (u ? war.y : war.x) * x0;
                float pz = D[(t + 8) * 4 + rh * 2 + u]  + (u ? brz.y : brz.x) + (u ? waz.y : waz.x) * x0;
                float pn = D[(t + 16) * 4 + rh * 2 + u] + (u ? bhn.y : bhn.x);
                float gx = (u ? bin.y : bin.x) + (u ? wan.y : wan.x) * x0;
                if (HASX1) {
                    pr = fmaf((u ? wbr.y : wbr.x), x1, pr);
                    pz = fmaf((u ? wbz.y : wbz.x), x1, pz);
                    gx = fmaf((u ? wbn.y : wbn.x), x1, gx);
                }
                float rr = sigmoid_fast(pr);
                float zz = sigmoid_fast(pz);
                float nn = tanh_fast(fmaf(rr, pn, gx));
                const int hi = t * 4 + rh * 2 + u;
                float hv = nn + zz * (hreg[hi] - nn);
                hreg[hi] = hv;
                hn[u] = hv;
            }
            __nv_bfloat16 h0 = __float2bfloat16_rn(hn[0]);
            __nv_bfloat16 h1 = __float2bfloat16_rn(hn[1]);
            __nv_bfloat162 hi2 = __halves2bfloat162(h0, h1);
            __nv_bfloat162 lo2 = __floats2bfloat162_rn(hn[0] - __bfloat162float(h0),
                                                       hn[1] - __bfloat162float(h1));
            const int lr = group + rh * 8;
            const uint32_t off = (uint32_t)(warp * 16 + lr) * 128u
                               + (uint32_t)(((t ^ group) << 4) + tg * 4);
            *(__nv_bfloat162*)(smem + OFF_AHI + off) = hi2;
            *(__nv_bfloat162*)(smem + OFF_ALO + off) = lo2;
        }
    }
}

// ===================== main kernel =====================
__global__ void __launch_bounds__(NT, 1) krnn_mma(
    const float* __restrict__ X,
    const float* __restrict__ enc_w_ih, const float* __restrict__ enc_w_hh,
    const float* __restrict__ enc_b_ih, const float* __restrict__ enc_b_hh,
    const float* __restrict__ dec_w_ih, const float* __restrict__ dec_w_hh,
    const float* __restrict__ dec_b_ih, const float* __restrict__ dec_b_hh,
    const float* __restrict__ lin1_w,   const float* __restrict__ lin1_b)
{
    extern __shared__ unsigned char smem[];
    const int tid   = threadIdx.x;
    const int l     = tid & 31;
    const int warp  = tid >> 5;
    const int c     = (CC - 1) - blockIdx.y;          // longest-first
    const uint32_t smb = smem_u32_of(smem);

    const int group = l >> 2;
    const int tg    = l & 3;
    // ldmatrix lane->row/chunk assignment (A: mats rows0-7/8-15 x klo/khi; B: n-tile pair)
    const int arow  = (l & 7) + ((l >> 3) & 1) * 8;
    const int acoff = (l >> 4) & 1;
    const int brow  = (l & 7) + ((l >> 4) & 1) * 8;
    const int bcoff = (l >> 3) & 1;
    const int sw7   = l & 7;

    const int seq_a = blockIdx.x * SEQ_PER_CTA + warp * 16 + group;
    const int seq_b = seq_a + 8;

    // stage ENCODER weights; zero A tiles (h = 0)
    stage_w(smem, tid, enc_w_hh + c * (G3 * HH), enc_w_ih + c * (G3 * 2), 2,
            enc_b_ih + c * G3, enc_b_hh + c * G3);
    {
        uint4 z; z.x = z.y = z.z = z.w = 0u;
        for (int i = tid * 16; i < 32768; i += NT * 16)
            *(uint4*)(smem + OFF_AHI + i) = z;
    }
    __syncthreads();

    float hreg[32];
    #pragma unroll
    for (int i = 0; i < 32; ++i) hreg[i] = 0.0f;

    const float* cf = (const float*)(smem + OFF_COEF);

    // ---- encoder ----
    const int s_enc = c + 3;
    const float2* hvp = (const float2*)g_hv;
    #pragma unroll 1
    for (int st = 0; st < s_enc; ++st) {
        float2 xa = hvp[(size_t)(c * TOUT + st) * BN + seq_a];
        float2 xb = hvp[(size_t)(c * TOUT + st) * BN + seq_b];
        mma_step<true>(smem, smb, cf, hreg, warp, group, tg,
                       arow, acoff, brow, bcoff, sw7, xa.x, xa.y, xb.x, xb.y);
    }

    // ---- restage DECODER weights ----
    __syncthreads();
    stage_w(smem, tid, dec_w_hh + c * (G3 * HH), dec_w_ih + c * G3, 1,
            dec_b_ih + c * G3, dec_b_hh + c * G3);
    __syncthreads();

    // preload lin1 weights for this thread's 16 gate columns
    float l1wr[16];
    #pragma unroll
    for (int t = 0; t < 8; ++t) {
        l1wr[t * 2]     = lin1_w[c * HH + t * 8 + tg * 2];
        l1wr[t * 2 + 1] = lin1_w[c * HH + t * 8 + tg * 2 + 1];
    }
    const float l1b = lin1_b[c];

    float va = X[(size_t)seq_a * (TT * 2) + 22];      // X[seq, t=11, f=0]
    float vb = X[(size_t)seq_b * (TT * 2) + 22];

    // ---- decoder ----
    #pragma unroll 1
    for (int st = 0; st < TOUT; ++st) {
        mma_step<false>(smem, smb, cf, hreg, warp, group, tg,
                        arow, acoff, brow, bcoff, sw7, va, 0.0f, vb, 0.0f);
        float pa = 0.0f, pb = 0.0f;
        #pragma unroll
        for (int t = 0; t < 8; ++t) {
            pa = fmaf(hreg[t * 4 + 0], l1wr[t * 2], pa);
            pa = fmaf(hreg[t * 4 + 1], l1wr[t * 2 + 1], pa);
            pb = fmaf(hreg[t * 4 + 2], l1wr[t * 2], pb);
            pb = fmaf(hreg[t * 4 + 3], l1wr[t * 2 + 1], pb);
        }
        pa += __shfl_xor_sync(0xffffffff, pa, 1);
        pa += __shfl_xor_sync(0xffffffff, pa, 2);
        pb += __shfl_xor_sync(0xffffffff, pb, 1);
        pb += __shfl_xor_sync(0xffffffff, pb, 2);
        va = pa + l1b;
        vb = pb + l1b;
        if (tg == 0) {
            g_vals[(size_t)(c * TOUT + st) * BN + seq_a] = va;
            g_vals[(size_t)(c * TOUT + st) * BN + seq_b] = vb;
        }
    }
}

// ===================== hv precompute =====================
__global__ void __launch_bounds__(256) krnn_hv(
    const float* __restrict__ X,
    const float* __restrict__ lin2_w, const float* __restrict__ lin2_b)
{
    const int seq = blockIdx.x * 256 + threadIdx.x;
    float Xl[24];
    {
        const float4* xp = (const float4*)(X + (size_t)seq * (TT * 2));
        #pragma unroll
        for (int q = 0; q < 6; ++q) {
            float4 v = xp[q];
            Xl[4*q+0] = v.x; Xl[4*q+1] = v.y; Xl[4*q+2] = v.z; Xl[4*q+3] = v.w;
        }
    }
    float2* hvp = (float2*)g_hv;
    for (int c = 0; c < CC; ++c) {
        const int s = c + 3;
        for (int st = 0; st < s; ++st) {
            float b = lin2_b[c * 12 + st];
            float x0 = b, x1 = b;
            #pragma unroll
            for (int t = 0; t < TT; ++t) {
                float w = lin2_w[c * 144 + st * 12 + t];
                x0 = fmaf(Xl[2 * t],     w, x0);
                x1 = fmaf(Xl[2 * t + 1], w, x1);
            }
            hvp[(size_t)(c * TOUT + st) * BN + seq] = make_float2(x0, x1);
        }
    }
}

// ===================== final combine =====================
__global__ void __launch_bounds__(256) krnn_combine(
    const float* __restrict__ X,
    const float* __restrict__ embed1,
    float* __restrict__ out)
{
    const int seq = blockIdx.x * 256 + threadIdx.x;

    float q[TT];
    #pragma unroll
    for (int t = 0; t < TT; ++t) q[t] = X[(size_t)seq * (TT * 2) + t * 2];

    float wq[TOUT];
    #pragma unroll
    for (int o = 0; o < TOUT; ++o) {
        float a = 0.0f;
        #pragma unroll
        for (int t = 0; t < TT; ++t) a = fmaf(q[t], embed1[t * TOUT + o], a);
        wq[o] = a;
    }

    float ov[TOUT * CC];
    #pragma unroll
    for (int cc = 0; cc < CC; ++cc)
        #pragma unroll
        for (int o = 0; o < TOUT; ++o)
            ov[o * CC + cc] = g_vals[((size_t)cc * TOUT + o) * BN + seq];

    float wc[CC];
    #pragma unroll
    for (int cc = 0; cc < CC; ++cc) {
        float a = 0.0f;
        #pragma unroll
        for (int o = 0; o < TOUT; ++o) a = fmaf(wq[o], ov[o * CC + cc], a);
        wc[cc] = a;
    }

    float m = wc[0];
    #pragma unroll
    for (int cc = 1; cc < CC; ++cc) m = fmaxf(m, wc[cc]);
    float e[CC]; float ssum = 0.0f;
    #pragma unroll
    for (int cc = 0; cc < CC; ++cc) { e[cc] = expf(wc[cc] - m); ssum += e[cc]; }
    float inv = 1.0f / ssum;

    #pragma unroll
    for (int o = 0; o < TOUT; ++o) {
        float a = 0.0f;
        #pragma unroll
        for (int cc = 0; cc < CC; ++cc) a = fmaf(ov[o * CC + cc], e[cc], a);
        out[(size_t)seq * TOUT + o] = a * inv;
    }
}

extern "C" void kernel_launch(void* const* d_in, const int* in_sizes, int n_in,
                              void* d_out, int out_size)
{
    const float* X        = (const float*)d_in[1];
    const float* enc_w_ih = (const float*)d_in[2];
    const float* enc_w_hh = (const float*)d_in[3];
    const float* enc_b_ih = (const float*)d_in[4];
    const float* enc_b_hh = (const float*)d_in[5];
    const float* dec_w_ih = (const float*)d_in[6];
    const float* dec_w_hh = (const float*)d_in[7];
    const float* dec_b_ih = (const float*)d_in[8];
    const float* dec_b_hh = (const float*)d_in[9];
    const float* lin1_w   = (const float*)d_in[10];
    const float* lin1_b   = (const float*)d_in[11];
    const float* lin2_w   = (const float*)d_in[12];
    const float* lin2_b   = (const float*)d_in[13];
    const float* embed1   = (const float*)d_in[14];

    cudaFuncSetAttribute(krnn_mma, cudaFuncAttributeMaxDynamicSharedMemorySize, SMEM_BYTES);

    krnn_hv<<<BN / 256, 256>>>(X, lin2_w, lin2_b);

    dim3 grid(BN / SEQ_PER_CTA, CC);
    krnn_mma<<<grid, NT, SMEM_BYTES>>>(
        X, enc_w_ih, enc_w_hh, enc_b_ih, enc_b_hh,
        dec_w_ih, dec_w_hh, dec_b_ih, dec_b_hh,
        lin1_w, lin1_b);

    krnn_combine<<<BN / 256, 256>>>(X, embed1, (float*)d_out);
}

// round 9
// speedup vs baseline: 3.4874x; 1.3926x over previous
#include <cuda_runtime.h>
#include <cuda_fp16.h>
#include <cstdint>

// Problem constants
#define BN    131072
#define TT    12
#define HH    64
#define G3    192
#define CC    10
#define TOUT  12
#define NT    256            // 8 warps; warp = 16 seqs; CTA = 128 seqs
#define SEQ_PER_CTA 128

// ---- SMEM byte offsets ----
#define OFF_A    0                 // h fp16: 128 rows x 128B (64 fp16), swizzled
#define OFF_WHI  16384             // W hi fp16: 192 rows x 128B, swizzled
#define OFF_WLO  40960             // W lo fp16
#define OFF_COEF 65536             // float arrays
#define CF_WA   0                  // w_ih feature0 [192]
#define CF_WB   192                // w_ih feature1 [192]
#define CF_BRZ  384                // b_ih+b_hh for r,z [128]
#define CF_BIHN 512                // b_ih n [64]
#define CF_BHHN 576                // b_hh n [64]
#define SMEM_BYTES (OFF_COEF + 640*4)

// device-global scratch
__device__ float g_hv[(size_t)CC * TOUT * BN * 2];   // encoder inputs (x0,x1)
__device__ float g_vals[(size_t)CC * TOUT * BN];     // decoder outputs

// ===================== helpers =====================
__device__ __forceinline__ uint32_t smem_u32_of(const void* p) {
    uint32_t a;
    asm("{ .reg .u64 t; cvta.to.shared.u64 t, %1; cvt.u32.u64 %0, t; }" : "=r"(a) : "l"(p));
    return a;
}
__device__ __forceinline__ float sigmoid_fast(float x) {
    float t, y = 0.5f * x;
    asm("tanh.approx.f32 %0, %1;" : "=f"(t) : "f"(y));
    return fmaf(0.5f, t, 0.5f);
}
__device__ __forceinline__ float tanh_fast(float x) {
    float t;
    asm("tanh.approx.f32 %0, %1;" : "=f"(t) : "f"(x));
    return t;
}

#define LDSM_X4(r0, r1, r2, r3, addr) \
    asm volatile("ldmatrix.sync.aligned.m8n8.x4.shared.b16 {%0,%1,%2,%3}, [%4];" \
                 : "=r"(r0), "=r"(r1), "=r"(r2), "=r"(r3) : "r"(addr))

#define MMA16816(dp, a0, a1, a2, a3, b0, b1) \
    asm volatile("mma.sync.aligned.m16n8k16.row.col.f32.f16.f16.f32 " \
                 "{%0,%1,%2,%3}, {%4,%5,%6,%7}, {%8,%9}, {%0,%1,%2,%3};" \
                 : "+f"((dp)[0]), "+f"((dp)[1]), "+f"((dp)[2]), "+f"((dp)[3]) \
                 : "r"(a0), "r"(a1), "r"(a2), "r"(a3), "r"(b0), "r"(b1))

// ===================== weight staging =====================
__device__ __forceinline__ void stage_w(
    unsigned char* smem, int tid,
    const float* __restrict__ whh, const float* __restrict__ wih, int stride,
    const float* __restrict__ bih, const float* __restrict__ bhh)
{
    for (int idx = tid; idx < G3 * HH; idx += NT) {
        int g = idx >> 6, k = idx & 63;
        float w = whh[idx];
        __half hi = __float2half_rn(w);
        __half lo = __float2half_rn(w - __half2float(hi));
        uint32_t off = (uint32_t)g * 128u + (uint32_t)((((k >> 3) ^ (g & 7)) << 4) + (k & 7) * 2);
        *(__half*)(smem + OFF_WHI + off) = hi;
        *(__half*)(smem + OFF_WLO + off) = lo;
    }
    float* cf = (float*)(smem + OFF_COEF);
    for (int t = tid; t < G3; t += NT) {
        cf[CF_WA + t] = wih[t * stride];
        cf[CF_WB + t] = (stride == 2) ? wih[t * 2 + 1] : 0.0f;
        float bi = bih[t], bh = bhh[t];
        if (t < 128) cf[CF_BRZ + t] = bi + bh;
        else { cf[CF_BIHN + t - 128] = bi; cf[CF_BHHN + t - 128] = bh; }
    }
}

// ===================== one GRU step (mma.sync, fp16 2-pass) =====================
// D = W·h with W = Whi + Wlo (fp16 split), h single fp16 tile.
// kcb-outer: A fragment loaded once per k16 chunk, reused by both W passes.
// hreg: fp32 h in D-fragment layout (index t*4 + rh*2 + u).
template<bool HASX1>
__device__ __forceinline__ void mma_step(
    unsigned char* smem, uint32_t smb, const float* cf, float* hreg,
    int warp, int group, int tg,
    int arow, int acoff, int brow, int bcoff, int sw7,
    float xa0, float xa1, float xb0, float xb1)
{
    float D[96];
    #pragma unroll
    for (int i = 0; i < 96; ++i) D[i] = 0.0f;

    __syncwarp();

    const uint32_t a_row_b = (uint32_t)(warp * 16 + arow) * 128u;

    #pragma unroll 1
    for (int kcb = 0; kcb < 4; ++kcb) {
        const int kc = kcb * 2;

        uint32_t A0, A1, A2, A3;
        uint32_t aaddr = smb + OFF_A + a_row_b + (uint32_t)(((kc + acoff) ^ sw7) << 4);
        LDSM_X4(A0, A1, A2, A3, aaddr);

        const uint32_t bsw = (uint32_t)(((kc + bcoff) ^ sw7) << 4);
        const uint32_t brb = (uint32_t)brow * 128u + bsw;
        #pragma unroll
        for (int bt = 0; bt < 12; ++bt) {
            const uint32_t brow_off = (uint32_t)(bt * 16) * 128u + brb;
            uint32_t H0, H1, H2, H3, L0, L1, L2, L3;
            LDSM_X4(H0, H1, H2, H3, smb + OFF_WHI + brow_off);
            LDSM_X4(L0, L1, L2, L3, smb + OFF_WLO + brow_off);
            MMA16816(&D[(2 * bt) * 4],     A0, A1, A2, A3, H0, H1);
            MMA16816(&D[(2 * bt + 1) * 4], A0, A1, A2, A3, H2, H3);
            MMA16816(&D[(2 * bt) * 4],     A0, A1, A2, A3, L0, L1);
            MMA16816(&D[(2 * bt + 1) * 4], A0, A1, A2, A3, L2, L3);
        }
    }

    __syncwarp();

    // ---- epilogue: gates, h update, fp16 store ----
    #pragma unroll
    for (int t = 0; t < 8; ++t) {
        const int g2 = t * 8 + tg * 2;
        float2 war = *(const float2*)(cf + CF_WA + g2);
        float2 waz = *(const float2*)(cf + CF_WA + 64 + g2);
        float2 wan = *(const float2*)(cf + CF_WA + 128 + g2);
        float2 brr = *(const float2*)(cf + CF_BRZ + g2);
        float2 brz = *(const float2*)(cf + CF_BRZ + 64 + g2);
        float2 bin = *(const float2*)(cf + CF_BIHN + g2);
        float2 bhn = *(const float2*)(cf + CF_BHHN + g2);
        float2 wbr, wbz, wbn;
        if (HASX1) {
            wbr = *(const float2*)(cf + CF_WB + g2);
            wbz = *(const float2*)(cf + CF_WB + 64 + g2);
            wbn = *(const float2*)(cf + CF_WB + 128 + g2);
        }
        #pragma unroll
        for (int rh = 0; rh < 2; ++rh) {
            const float x0 = rh ? xb0 : xa0;
            const float x1 = rh ? xb1 : xa1;
            float hn[2];
            #pragma unroll
            for (int u = 0; u < 2; ++u) {
                float pr = D[t * 4 + rh * 2 + u]        + (u ? brr.y : brr.x) + (u ? war.y : war.x) * x0;
                float pz = D[(t + 8) * 4 + rh * 2 + u]  + (u ? brz.y : brz.x) + (u ? waz.y : waz.x) * x0;
                float pn = D[(t + 16) * 4 + rh * 2 + u] + (u ? bhn.y : bhn.x);
                float gx = (u ? bin.y : bin.x) + (u ? wan.y : wan.x) * x0;
                if (HASX1) {
                    pr = fmaf((u ? wbr.y : wbr.x), x1, pr);
                    pz = fmaf((u ? wbz.y : wbz.x), x1, pz);
                    gx = fmaf((u ? wbn.y : wbn.x), x1, gx);
                }
                float rr = sigmoid_fast(pr);
                float zz = sigmoid_fast(pz);
                float nn = tanh_fast(fmaf(rr, pn, gx));
                const int hi = t * 4 + rh * 2 + u;
                float hv = nn + zz * (hreg[hi] - nn);
                hreg[hi] = hv;
                hn[u] = hv;
            }
            __half2 h2 = __floats2half2_rn(hn[0], hn[1]);
            const int lr = group + rh * 8;
            const uint32_t off = (uint32_t)(warp * 16 + lr) * 128u
                               + (uint32_t)(((t ^ group) << 4) + tg * 4);
            *(__half2*)(smem + OFF_A + off) = h2;
        }
    }
}

// ===================== main kernel =====================
__global__ void __launch_bounds__(NT, 1) krnn_mma(
    const float* __restrict__ X,
    const float* __restrict__ enc_w_ih, const float* __restrict__ enc_w_hh,
    const float* __restrict__ enc_b_ih, const float* __restrict__ enc_b_hh,
    const float* __restrict__ dec_w_ih, const float* __restrict__ dec_w_hh,
    const float* __restrict__ dec_b_ih, const float* __restrict__ dec_b_hh,
    const float* __restrict__ lin1_w,   const float* __restrict__ lin1_b)
{
    extern __shared__ unsigned char smem[];
    const int tid   = threadIdx.x;
    const int l     = tid & 31;
    const int warp  = tid >> 5;
    const int c     = (CC - 1) - blockIdx.y;          // longest-first
    const uint32_t smb = smem_u32_of(smem);

    const int group = l >> 2;
    const int tg    = l & 3;
    const int arow  = (l & 7) + ((l >> 3) & 1) * 8;
    const int acoff = (l >> 4) & 1;
    const int brow  = (l & 7) + ((l >> 4) & 1) * 8;
    const int bcoff = (l >> 3) & 1;
    const int sw7   = l & 7;

    const int seq_a = blockIdx.x * SEQ_PER_CTA + warp * 16 + group;
    const int seq_b = seq_a + 8;

    // stage ENCODER weights; zero A tile (h = 0)
    stage_w(smem, tid, enc_w_hh + c * (G3 * HH), enc_w_ih + c * (G3 * 2), 2,
            enc_b_ih + c * G3, enc_b_hh + c * G3);
    {
        uint4 z; z.x = z.y = z.z = z.w = 0u;
        for (int i = tid * 16; i < 16384; i += NT * 16)
            *(uint4*)(smem + OFF_A + i) = z;
    }
    __syncthreads();

    float hreg[32];
    #pragma unroll
    for (int i = 0; i < 32; ++i) hreg[i] = 0.0f;

    const float* cf = (const float*)(smem + OFF_COEF);

    // ---- encoder ----
    const int s_enc = c + 3;
    const float2* hvp = (const float2*)g_hv;
    #pragma unroll 1
    for (int st = 0; st < s_enc; ++st) {
        float2 xa = hvp[(size_t)(c * TOUT + st) * BN + seq_a];
        float2 xb = hvp[(size_t)(c * TOUT + st) * BN + seq_b];
        mma_step<true>(smem, smb, cf, hreg, warp, group, tg,
                       arow, acoff, brow, bcoff, sw7, xa.x, xa.y, xb.x, xb.y);
    }

    // ---- restage DECODER weights ----
    __syncthreads();
    stage_w(smem, tid, dec_w_hh + c * (G3 * HH), dec_w_ih + c * G3, 1,
            dec_b_ih + c * G3, dec_b_hh + c * G3);
    __syncthreads();

    // preload lin1 weights for this thread's 16 gate columns
    float l1wr[16];
    #pragma unroll
    for (int t = 0; t < 8; ++t) {
        l1wr[t * 2]     = lin1_w[c * HH + t * 8 + tg * 2];
        l1wr[t * 2 + 1] = lin1_w[c * HH + t * 8 + tg * 2 + 1];
    }
    const float l1b = lin1_b[c];

    float va = X[(size_t)seq_a * (TT * 2) + 22];      // X[seq, t=11, f=0]
    float vb = X[(size_t)seq_b * (TT * 2) + 22];

    // ---- decoder ----
    #pragma unroll 1
    for (int st = 0; st < TOUT; ++st) {
        mma_step<false>(smem, smb, cf, hreg, warp, group, tg,
                        arow, acoff, brow, bcoff, sw7, va, 0.0f, vb, 0.0f);
        float pa = 0.0f, pb = 0.0f;
        #pragma unroll
        for (int t = 0; t < 8; ++t) {
            pa = fmaf(hreg[t * 4 + 0], l1wr[t * 2], pa);
            pa = fmaf(hreg[t * 4 + 1], l1wr[t * 2 + 1], pa);
            pb = fmaf(hreg[t * 4 + 2], l1wr[t * 2], pb);
            pb = fmaf(hreg[t * 4 + 3], l1wr[t * 2 + 1], pb);
        }
        pa += __shfl_xor_sync(0xffffffff, pa, 1);
        pa += __shfl_xor_sync(0xffffffff, pa, 2);
        pb += __shfl_xor_sync(0xffffffff, pb, 1);
        pb += __shfl_xor_sync(0xffffffff, pb, 2);
        va = pa + l1b;
        vb = pb + l1b;
        if (tg == 0) {
            g_vals[(size_t)(c * TOUT + st) * BN + seq_a] = va;
            g_vals[(size_t)(c * TOUT + st) * BN + seq_b] = vb;
        }
    }
}

// ===================== hv precompute =====================
__global__ void __launch_bounds__(256) krnn_hv(
    const float* __restrict__ X,
    const float* __restrict__ lin2_w, const float* __restrict__ lin2_b)
{
    const int seq = blockIdx.x * 256 + threadIdx.x;
    float Xl[24];
    {
        const float4* xp = (const float4*)(X + (size_t)seq * (TT * 2));
        #pragma unroll
        for (int q = 0; q < 6; ++q) {
            float4 v = xp[q];
            Xl[4*q+0] = v.x; Xl[4*q+1] = v.y; Xl[4*q+2] = v.z; Xl[4*q+3] = v.w;
        }
    }
    float2* hvp = (float2*)g_hv;
    for (int c = 0; c < CC; ++c) {
        const int s = c + 3;
        for (int st = 0; st < s; ++st) {
            float b = lin2_b[c * 12 + st];
            float x0 = b, x1 = b;
            #pragma unroll
            for (int t = 0; t < TT; ++t) {
                float w = lin2_w[c * 144 + st * 12 + t];
                x0 = fmaf(Xl[2 * t],     w, x0);
                x1 = fmaf(Xl[2 * t + 1], w, x1);
            }
            hvp[(size_t)(c * TOUT + st) * BN + seq] = make_float2(x0, x1);
        }
    }
}

// ===================== final combine =====================
__global__ void __launch_bounds__(256) krnn_combine(
    const float* __restrict__ X,
    const float* __restrict__ embed1,
    float* __restrict__ out)
{
    const int seq = blockIdx.x * 256 + threadIdx.x;

    float q[TT];
    #pragma unroll
    for (int t = 0; t < TT; ++t) q[t] = X[(size_t)seq * (TT * 2) + t * 2];

    float wq[TOUT];
    #pragma unroll
    for (int o = 0; o < TOUT; ++o) {
        float a = 0.0f;
        #pragma unroll
        for (int t = 0; t < TT; ++t) a = fmaf(q[t], embed1[t * TOUT + o], a);
        wq[o] = a;
    }

    float ov[TOUT * CC];
    #pragma unroll
    for (int cc = 0; cc < CC; ++cc)
        #pragma unroll
        for (int o = 0; o < TOUT; ++o)
            ov[o * CC + cc] = g_vals[((size_t)cc * TOUT + o) * BN + seq];

    float wc[CC];
    #pragma unroll
    for (int cc = 0; cc < CC; ++cc) {
        float a = 0.0f;
        #pragma unroll
        for (int o = 0; o < TOUT; ++o) a = fmaf(wq[o], ov[o * CC + cc], a);
        wc[cc] = a;
    }

    float m = wc[0];
    #pragma unroll
    for (int cc = 1; cc < CC; ++cc) m = fmaxf(m, wc[cc]);
    float e[CC]; float ssum = 0.0f;
    #pragma unroll
    for (int cc = 0; cc < CC; ++cc) { e[cc] = expf(wc[cc] - m); ssum += e[cc]; }
    float inv = 1.0f / ssum;

    #pragma unroll
    for (int o = 0; o < TOUT; ++o) {
        float a = 0.0f;
        #pragma unroll
        for (int cc = 0; cc < CC; ++cc) a = fmaf(ov[o * CC + cc], e[cc], a);
        out[(size_t)seq * TOUT + o] = a * inv;
    }
}

extern "C" void kernel_launch(void* const* d_in, const int* in_sizes, int n_in,
                              void* d_out, int out_size)
{
    const float* X        = (const float*)d_in[1];
    const float* enc_w_ih = (const float*)d_in[2];
    const float* enc_w_hh = (const float*)d_in[3];
    const float* enc_b_ih = (const float*)d_in[4];
    const float* enc_b_hh = (const float*)d_in[5];
    const float* dec_w_ih = (const float*)d_in[6];
    const float* dec_w_hh = (const float*)d_in[7];
    const float* dec_b_ih = (const float*)d_in[8];
    const float* dec_b_hh = (const float*)d_in[9];
    const float* lin1_w   = (const float*)d_in[10];
    const float* lin1_b   = (const float*)d_in[11];
    const float* lin2_w   = (const float*)d_in[12];
    const float* lin2_b   = (const float*)d_in[13];
    const float* embed1   = (const float*)d_in[14];

    cudaFuncSetAttribute(krnn_mma, cudaFuncAttributeMaxDynamicSharedMemorySize, SMEM_BYTES);

    krnn_hv<<<BN / 256, 256>>>(X, lin2_w, lin2_b);

    dim3 grid(BN / SEQ_PER_CTA, CC);
    krnn_mma<<<grid, NT, SMEM_BYTES>>>(
        X, enc_w_ih, enc_w_hh, enc_b_ih, enc_b_hh,
        dec_w_ih, dec_w_hh, dec_b_ih, dec_b_hh,
        lin1_w, lin1_b);

    krnn_combine<<<BN / 256, 256>>>(X, embed1, (float*)d_out);
}

// round 10
// speedup vs baseline: 4.6854x; 1.3435x over previous
#include <cuda_runtime.h>
#include <cuda_fp16.h>
#include <cstdint>

// Problem constants
#define BN    131072
#define TT    12
#define HH    64
#define G3    192
#define CC    10
#define TOUT  12
#define NT    256            // 8 warps; warp = 16 seqs; CTA = 128 seqs
#define SEQ_PER_CTA 128

// ---- SMEM byte offsets ----
#define OFF_A    0                 // h fp16: 128 rows x 128B (64 fp16), swizzled
#define OFF_W    16384             // W fp16: 192 rows x 128B, swizzled
#define OFF_COEF 40960             // float arrays
#define CF_WA   0                  // w_ih feature0 [192]
#define CF_WB   192                // w_ih feature1 [192]
#define CF_BRZ  384                // b_ih+b_hh for r,z [128]
#define CF_BIHN 512                // b_ih n [64]
#define CF_BHHN 576                // b_hh n [64]
#define SMEM_BYTES (OFF_COEF + 640*4)

// device-global scratch
__device__ float g_hv[(size_t)CC * TOUT * BN * 2];   // encoder inputs (x0,x1)
__device__ float g_vals[(size_t)CC * TOUT * BN];     // decoder outputs

// ===================== helpers =====================
__device__ __forceinline__ uint32_t smem_u32_of(const void* p) {
    uint32_t a;
    asm("{ .reg .u64 t; cvta.to.shared.u64 t, %1; cvt.u32.u64 %0, t; }" : "=r"(a) : "l"(p));
    return a;
}
__device__ __forceinline__ float sigmoid_fast(float x) {
    float t, y = 0.5f * x;
    asm("tanh.approx.f32 %0, %1;" : "=f"(t) : "f"(y));
    return fmaf(0.5f, t, 0.5f);
}
__device__ __forceinline__ float tanh_fast(float x) {
    float t;
    asm("tanh.approx.f32 %0, %1;" : "=f"(t) : "f"(x));
    return t;
}

#define LDSM_X4(r0, r1, r2, r3, addr) \
    asm volatile("ldmatrix.sync.aligned.m8n8.x4.shared.b16 {%0,%1,%2,%3}, [%4];" \
                 : "=r"(r0), "=r"(r1), "=r"(r2), "=r"(r3) : "r"(addr))

#define MMA16816(dp, a0, a1, a2, a3, b0, b1) \
    asm volatile("mma.sync.aligned.m16n8k16.row.col.f32.f16.f16.f32 " \
                 "{%0,%1,%2,%3}, {%4,%5,%6,%7}, {%8,%9}, {%0,%1,%2,%3};" \
                 : "+f"((dp)[0]), "+f"((dp)[1]), "+f"((dp)[2]), "+f"((dp)[3]) \
                 : "r"(a0), "r"(a1), "r"(a2), "r"(a3), "r"(b0), "r"(b1))

// ===================== weight staging =====================
__device__ __forceinline__ void stage_w(
    unsigned char* smem, int tid,
    const float* __restrict__ whh, const float* __restrict__ wih, int stride,
    const float* __restrict__ bih, const float* __restrict__ bhh)
{
    for (int idx = tid; idx < G3 * HH; idx += NT) {
        int g = idx >> 6, k = idx & 63;
        __half hi = __float2half_rn(whh[idx]);
        uint32_t off = (uint32_t)g * 128u + (uint32_t)((((k >> 3) ^ (g & 7)) << 4) + (k & 7) * 2);
        *(__half*)(smem + OFF_W + off) = hi;
    }
    float* cf = (float*)(smem + OFF_COEF);
    for (int t = tid; t < G3; t += NT) {
        cf[CF_WA + t] = wih[t * stride];
        cf[CF_WB + t] = (stride == 2) ? wih[t * 2 + 1] : 0.0f;
        float bi = bih[t], bh = bhh[t];
        if (t < 128) cf[CF_BRZ + t] = bi + bh;
        else { cf[CF_BIHN + t - 128] = bi; cf[CF_BHHN + t - 128] = bh; }
    }
}

// ===================== one GRU step (mma.sync, fp16 single-pass) =====================
// D = W·h, W and h fp16 (error damped by GRU gating; measured ladder says safe).
// hreg: fp32 h in D-fragment layout (index t*4 + rh*2 + u).
template<bool HASX1>
__device__ __forceinline__ void mma_step(
    unsigned char* smem, uint32_t smb, const float* cf, float* hreg,
    int warp, int group, int tg,
    int arow, int acoff, int brow, int bcoff, int sw7,
    float xa0, float xa1, float xb0, float xb1)
{
    float D[96];
    #pragma unroll
    for (int i = 0; i < 96; ++i) D[i] = 0.0f;

    __syncwarp();

    const uint32_t a_row_b = (uint32_t)(warp * 16 + arow) * 128u;

    #pragma unroll 1
    for (int kcb = 0; kcb < 4; ++kcb) {
        const int kc = kcb * 2;

        uint32_t A0, A1, A2, A3;
        uint32_t aaddr = smb + OFF_A + a_row_b + (uint32_t)(((kc + acoff) ^ sw7) << 4);
        LDSM_X4(A0, A1, A2, A3, aaddr);

        const uint32_t bsw = (uint32_t)(((kc + bcoff) ^ sw7) << 4);
        const uint32_t brb = (uint32_t)brow * 128u + bsw;
        #pragma unroll
        for (int bt = 0; bt < 12; ++bt) {
            const uint32_t brow_off = (uint32_t)(bt * 16) * 128u + brb;
            uint32_t B0, B1, B2, B3;
            LDSM_X4(B0, B1, B2, B3, smb + OFF_W + brow_off);
            MMA16816(&D[(2 * bt) * 4],     A0, A1, A2, A3, B0, B1);
            MMA16816(&D[(2 * bt + 1) * 4], A0, A1, A2, A3, B2, B3);
        }
    }

    __syncwarp();

    // ---- epilogue: gates, h update, fp16 store ----
    #pragma unroll
    for (int t = 0; t < 8; ++t) {
        const int g2 = t * 8 + tg * 2;
        float2 war = *(const float2*)(cf + CF_WA + g2);
        float2 waz = *(const float2*)(cf + CF_WA + 64 + g2);
        float2 wan = *(const float2*)(cf + CF_WA + 128 + g2);
        float2 brr = *(const float2*)(cf + CF_BRZ + g2);
        float2 brz = *(const float2*)(cf + CF_BRZ + 64 + g2);
        float2 bin = *(const float2*)(cf + CF_BIHN + g2);
        float2 bhn = *(const float2*)(cf + CF_BHHN + g2);
        float2 wbr, wbz, wbn;
        if (HASX1) {
            wbr = *(const float2*)(cf + CF_WB + g2);
            wbz = *(const float2*)(cf + CF_WB + 64 + g2);
            wbn = *(const float2*)(cf + CF_WB + 128 + g2);
        }
        #pragma unroll
        for (int rh = 0; rh < 2; ++rh) {
            const float x0 = rh ? xb0 : xa0;
            const float x1 = rh ? xb1 : xa1;
            float hn[2];
            #pragma unroll
            for (int u = 0; u < 2; ++u) {
                float pr = D[t * 4 + rh * 2 + u]        + (u ? brr.y : brr.x) + (u ? war.y : war.x) * x0;
                float pz = D[(t + 8) * 4 + rh * 2 + u]  + (u ? brz.y : brz.x) + (u ? waz.y : waz.x) * x0;
                float pn = D[(t + 16) * 4 + rh * 2 + u] + (u ? bhn.y : bhn.x);
                float gx = (u ? bin.y : bin.x) + (u ? wan.y : wan.x) * x0;
                if (HASX1) {
                    pr = fmaf((u ? wbr.y : wbr.x), x1, pr);
                    pz = fmaf((u ? wbz.y : wbz.x), x1, pz);
                    gx = fmaf((u ? wbn.y : wbn.x), x1, gx);
                }
                float rr = sigmoid_fast(pr);
                float zz = sigmoid_fast(pz);
                float nn = tanh_fast(fmaf(rr, pn, gx));
                const int hi = t * 4 + rh * 2 + u;
                float hv = nn + zz * (hreg[hi] - nn);
                hreg[hi] = hv;
                hn[u] = hv;
            }
            __half2 h2 = __floats2half2_rn(hn[0], hn[1]);
            const int lr = group + rh * 8;
            const uint32_t off = (uint32_t)(warp * 16 + lr) * 128u
                               + (uint32_t)(((t ^ group) << 4) + tg * 4);
            *(__half2*)(smem + OFF_A + off) = h2;
        }
    }
}

// ===================== main kernel =====================
__global__ void __launch_bounds__(NT, 1) krnn_mma(
    const float* __restrict__ X,
    const float* __restrict__ enc_w_ih, const float* __restrict__ enc_w_hh,
    const float* __restrict__ enc_b_ih, const float* __restrict__ enc_b_hh,
    const float* __restrict__ dec_w_ih, const float* __restrict__ dec_w_hh,
    const float* __restrict__ dec_b_ih, const float* __restrict__ dec_b_hh,
    const float* __restrict__ lin1_w,   const float* __restrict__ lin1_b)
{
    extern __shared__ unsigned char smem[];
    const int tid   = threadIdx.x;
    const int l     = tid & 31;
    const int warp  = tid >> 5;
    const int c     = (CC - 1) - blockIdx.y;          // longest-first
    const uint32_t smb = smem_u32_of(smem);

    const int group = l >> 2;
    const int tg    = l & 3;
    const int arow  = (l & 7) + ((l >> 3) & 1) * 8;
    const int acoff = (l >> 4) & 1;
    const int brow  = (l & 7) + ((l >> 4) & 1) * 8;
    const int bcoff = (l >> 3) & 1;
    const int sw7   = l & 7;

    const int seq_a = blockIdx.x * SEQ_PER_CTA + warp * 16 + group;
    const int seq_b = seq_a + 8;

    // stage ENCODER weights; zero A tile (h = 0)
    stage_w(smem, tid, enc_w_hh + c * (G3 * HH), enc_w_ih + c * (G3 * 2), 2,
            enc_b_ih + c * G3, enc_b_hh + c * G3);
    {
        uint4 z; z.x = z.y = z.z = z.w = 0u;
        for (int i = tid * 16; i < 16384; i += NT * 16)
            *(uint4*)(smem + OFF_A + i) = z;
    }
    __syncthreads();

    float hreg[32];
    #pragma unroll
    for (int i = 0; i < 32; ++i) hreg[i] = 0.0f;

    const float* cf = (const float*)(smem + OFF_COEF);

    // ---- encoder ----
    const int s_enc = c + 3;
    const float2* hvp = (const float2*)g_hv;
    #pragma unroll 1
    for (int st = 0; st < s_enc; ++st) {
        float2 xa = hvp[(size_t)(c * TOUT + st) * BN + seq_a];
        float2 xb = hvp[(size_t)(c * TOUT + st) * BN + seq_b];
        mma_step<true>(smem, smb, cf, hreg, warp, group, tg,
                       arow, acoff, brow, bcoff, sw7, xa.x, xa.y, xb.x, xb.y);
    }

    // ---- restage DECODER weights ----
    __syncthreads();
    stage_w(smem, tid, dec_w_hh + c * (G3 * HH), dec_w_ih + c * G3, 1,
            dec_b_ih + c * G3, dec_b_hh + c * G3);
    __syncthreads();

    // preload lin1 weights for this thread's 16 gate columns
    float l1wr[16];
    #pragma unroll
    for (int t = 0; t < 8; ++t) {
        l1wr[t * 2]     = lin1_w[c * HH + t * 8 + tg * 2];
        l1wr[t * 2 + 1] = lin1_w[c * HH + t * 8 + tg * 2 + 1];
    }
    const float l1b = lin1_b[c];

    float va = X[(size_t)seq_a * (TT * 2) + 22];      // X[seq, t=11, f=0]
    float vb = X[(size_t)seq_b * (TT * 2) + 22];

    // ---- decoder ----
    #pragma unroll 1
    for (int st = 0; st < TOUT; ++st) {
        mma_step<false>(smem, smb, cf, hreg, warp, group, tg,
                        arow, acoff, brow, bcoff, sw7, va, 0.0f, vb, 0.0f);
        float pa = 0.0f, pb = 0.0f;
        #pragma unroll
        for (int t = 0; t < 8; ++t) {
            pa = fmaf(hreg[t * 4 + 0], l1wr[t * 2], pa);
            pa = fmaf(hreg[t * 4 + 1], l1wr[t * 2 + 1], pa);
            pb = fmaf(hreg[t * 4 + 2], l1wr[t * 2], pb);
            pb = fmaf(hreg[t * 4 + 3], l1wr[t * 2 + 1], pb);
        }
        pa += __shfl_xor_sync(0xffffffff, pa, 1);
        pa += __shfl_xor_sync(0xffffffff, pa, 2);
        pb += __shfl_xor_sync(0xffffffff, pb, 1);
        pb += __shfl_xor_sync(0xffffffff, pb, 2);
        va = pa + l1b;
        vb = pb + l1b;
        if (tg == 0) {
            g_vals[(size_t)(c * TOUT + st) * BN + seq_a] = va;
            g_vals[(size_t)(c * TOUT + st) * BN + seq_b] = vb;
        }
    }
}

// ===================== hv precompute =====================
__global__ void __launch_bounds__(256) krnn_hv(
    const float* __restrict__ X,
    const float* __restrict__ lin2_w, const float* __restrict__ lin2_b)
{
    const int seq = blockIdx.x * 256 + threadIdx.x;
    float Xl[24];
    {
        const float4* xp = (const float4*)(X + (size_t)seq * (TT * 2));
        #pragma unroll
        for (int q = 0; q < 6; ++q) {
            float4 v = xp[q];
            Xl[4*q+0] = v.x; Xl[4*q+1] = v.y; Xl[4*q+2] = v.z; Xl[4*q+3] = v.w;
        }
    }
    float2* hvp = (float2*)g_hv;
    for (int c = 0; c < CC; ++c) {
        const int s = c + 3;
        for (int st = 0; st < s; ++st) {
            float b = lin2_b[c * 12 + st];
            float x0 = b, x1 = b;
            #pragma unroll
            for (int t = 0; t < TT; ++t) {
                float w = lin2_w[c * 144 + st * 12 + t];
                x0 = fmaf(Xl[2 * t],     w, x0);
                x1 = fmaf(Xl[2 * t + 1], w, x1);
            }
            hvp[(size_t)(c * TOUT + st) * BN + seq] = make_float2(x0, x1);
        }
    }
}

// ===================== final combine =====================
__global__ void __launch_bounds__(256) krnn_combine(
    const float* __restrict__ X,
    const float* __restrict__ embed1,
    float* __restrict__ out)
{
    const int seq = blockIdx.x * 256 + threadIdx.x;

    float q[TT];
    #pragma unroll
    for (int t = 0; t < TT; ++t) q[t] = X[(size_t)seq * (TT * 2) + t * 2];

    float wq[TOUT];
    #pragma unroll
    for (int o = 0; o < TOUT; ++o) {
        float a = 0.0f;
        #pragma unroll
        for (int t = 0; t < TT; ++t) a = fmaf(q[t], embed1[t * TOUT + o], a);
        wq[o] = a;
    }

    float ov[TOUT * CC];
    #pragma unroll
    for (int cc = 0; cc < CC; ++cc)
        #pragma unroll
        for (int o = 0; o < TOUT; ++o)
            ov[o * CC + cc] = g_vals[((size_t)cc * TOUT + o) * BN + seq];

    float wc[CC];
    #pragma unroll
    for (int cc = 0; cc < CC; ++cc) {
        float a = 0.0f;
        #pragma unroll
        for (int o = 0; o < TOUT; ++o) a = fmaf(wq[o], ov[o * CC + cc], a);
        wc[cc] = a;
    }

    float m = wc[0];
    #pragma unroll
    for (int cc = 1; cc < CC; ++cc) m = fmaxf(m, wc[cc]);
    float e[CC]; float ssum = 0.0f;
    #pragma unroll
    for (int cc = 0; cc < CC; ++cc) { e[cc] = expf(wc[cc] - m); ssum += e[cc]; }
    float inv = 1.0f / ssum;

    #pragma unroll
    for (int o = 0; o < TOUT; ++o) {
        float a = 0.0f;
        #pragma unroll
        for (int cc = 0; cc < CC; ++cc) a = fmaf(ov[o * CC + cc], e[cc], a);
        out[(size_t)seq * TOUT + o] = a * inv;
    }
}

extern "C" void kernel_launch(void* const* d_in, const int* in_sizes, int n_in,
                              void* d_out, int out_size)
{
    const float* X        = (const float*)d_in[1];
    const float* enc_w_ih = (const float*)d_in[2];
    const float* enc_w_hh = (const float*)d_in[3];
    const float* enc_b_ih = (const float*)d_in[4];
    const float* enc_b_hh = (const float*)d_in[5];
    const float* dec_w_ih = (const float*)d_in[6];
    const float* dec_w_hh = (const float*)d_in[7];
    const float* dec_b_ih = (const float*)d_in[8];
    const float* dec_b_hh = (const float*)d_in[9];
    const float* lin1_w   = (const float*)d_in[10];
    const float* lin1_b   = (const float*)d_in[11];
    const float* lin2_w   = (const float*)d_in[12];
    const float* lin2_b   = (const float*)d_in[13];
    const float* embed1   = (const float*)d_in[14];

    cudaFuncSetAttribute(krnn_mma, cudaFuncAttributeMaxDynamicSharedMemorySize, SMEM_BYTES);

    krnn_hv<<<BN / 256, 256>>>(X, lin2_w, lin2_b);

    dim3 grid(BN / SEQ_PER_CTA, CC);
    krnn_mma<<<grid, NT, SMEM_BYTES>>>(
        X, enc_w_ih, enc_w_hh, enc_b_ih, enc_b_hh,
        dec_w_ih, dec_w_hh, dec_b_ih, dec_b_hh,
        lin1_w, lin1_b);

    krnn_combine<<<BN / 256, 256>>>(X, embed1, (float*)d_out);
}

// round 11
// speedup vs baseline: 5.7610x; 1.2296x over previous
#include <cuda_runtime.h>
#include <cuda_fp16.h>
#include <cstdint>

// Problem constants
#define BN    131072
#define TT    12
#define HH    64
#define G3    192
#define CC    10
#define TOUT  12
#define NT    256            // 8 warps; warp = 16 seqs; CTA = 128 seqs
#define SEQ_PER_CTA 128

// ---- SMEM byte offsets ----
#define OFF_A    0                 // h fp16: 128 rows x 128B (64 fp16), swizzled
#define OFF_W    16384             // W fp16: 192 rows x 128B, swizzled
#define OFF_COEF 40960             // float arrays
#define CF_WA   0                  // w_ih feature0 [192]
#define CF_WB   192                // w_ih feature1 [192]
#define CF_BRZ  384                // b_ih+b_hh for r,z [128]
#define CF_BIHN 512                // b_ih n [64]
#define CF_BHHN 576                // b_hh n [64]
#define CF_L1W  640                // lin1 weights [64]
#define CF_L1B  704                // lin1 bias [1]
#define SMEM_BYTES (OFF_COEF + 708*4)

// device-global scratch
__device__ float g_hv[(size_t)CC * TOUT * BN * 2];   // encoder inputs (x0,x1)
__device__ float g_vals[(size_t)CC * TOUT * BN];     // decoder outputs

// ===================== helpers =====================
__device__ __forceinline__ uint32_t smem_u32_of(const void* p) {
    uint32_t a;
    asm("{ .reg .u64 t; cvta.to.shared.u64 t, %1; cvt.u32.u64 %0, t; }" : "=r"(a) : "l"(p));
    return a;
}
__device__ __forceinline__ float sigmoid_fast(float x) {
    float t, y = 0.5f * x;
    asm("tanh.approx.f32 %0, %1;" : "=f"(t) : "f"(y));
    return fmaf(0.5f, t, 0.5f);
}
__device__ __forceinline__ float tanh_fast(float x) {
    float t;
    asm("tanh.approx.f32 %0, %1;" : "=f"(t) : "f"(x));
    return t;
}

#define LDSM_X4(r0, r1, r2, r3, addr) \
    asm volatile("ldmatrix.sync.aligned.m8n8.x4.shared.b16 {%0,%1,%2,%3}, [%4];" \
                 : "=r"(r0), "=r"(r1), "=r"(r2), "=r"(r3) : "r"(addr))

#define MMA16816(dp, a0, a1, a2, a3, b0, b1) \
    asm volatile("mma.sync.aligned.m16n8k16.row.col.f32.f16.f16.f32 " \
                 "{%0,%1,%2,%3}, {%4,%5,%6,%7}, {%8,%9}, {%0,%1,%2,%3};" \
                 : "+f"((dp)[0]), "+f"((dp)[1]), "+f"((dp)[2]), "+f"((dp)[3]) \
                 : "r"(a0), "r"(a1), "r"(a2), "r"(a3), "r"(b0), "r"(b1))

// ===================== weight staging =====================
__device__ __forceinline__ void stage_w(
    unsigned char* smem, int tid,
    const float* __restrict__ whh, const float* __restrict__ wih, int stride,
    const float* __restrict__ bih, const float* __restrict__ bhh,
    const float* __restrict__ l1w, const float* __restrict__ l1b)
{
    for (int idx = tid; idx < G3 * HH; idx += NT) {
        int g = idx >> 6, k = idx & 63;
        __half hi = __float2half_rn(whh[idx]);
        uint32_t off = (uint32_t)g * 128u + (uint32_t)((((k >> 3) ^ (g & 7)) << 4) + (k & 7) * 2);
        *(__half*)(smem + OFF_W + off) = hi;
    }
    float* cf = (float*)(smem + OFF_COEF);
    for (int t = tid; t < G3; t += NT) {
        cf[CF_WA + t] = wih[t * stride];
        cf[CF_WB + t] = (stride == 2) ? wih[t * 2 + 1] : 0.0f;
        float bi = bih[t], bh = bhh[t];
        if (t < 128) cf[CF_BRZ + t] = bi + bh;
        else { cf[CF_BIHN + t - 128] = bi; cf[CF_BHHN + t - 128] = bh; }
    }
    if (tid < HH)  cf[CF_L1W + tid] = l1w[tid];
    if (tid == HH) cf[CF_L1B] = l1b[0];
}

// ===================== one GRU step (mma.sync, fp16, h in smem only) ===========
// D = W·h, W and h fp16. Old h ("hold") is read back from the A tile (the value
// this thread stored there last step), so NO register-resident h: cuts ~32 regs,
// enabling 2 CTAs/SM (4 warps/SMSP) to keep the tensor pipe fed during epilogues.
// WANTV: fuse the lin1 dot (fp32) into the epilogue; pa/pb partial dots returned.
template<bool HASX1, bool WANTV>
__device__ __forceinline__ void mma_step(
    unsigned char* smem, uint32_t smb, const float* cf,
    int warp, int group, int tg,
    int arow, int acoff, int brow, int bcoff, int sw7,
    float xa0, float xa1, float xb0, float xb1,
    float& va_out, float& vb_out)
{
    float D[96];
    #pragma unroll
    for (int i = 0; i < 96; ++i) D[i] = 0.0f;

    __syncwarp();

    const uint32_t a_row_b = (uint32_t)(warp * 16 + arow) * 128u;

    #pragma unroll 1
    for (int kcb = 0; kcb < 4; ++kcb) {
        const int kc = kcb * 2;

        uint32_t A0, A1, A2, A3;
        uint32_t aaddr = smb + OFF_A + a_row_b + (uint32_t)(((kc + acoff) ^ sw7) << 4);
        LDSM_X4(A0, A1, A2, A3, aaddr);

        const uint32_t bsw = (uint32_t)(((kc + bcoff) ^ sw7) << 4);
        const uint32_t brb = (uint32_t)brow * 128u + bsw;
        #pragma unroll
        for (int bt = 0; bt < 12; ++bt) {
            const uint32_t brow_off = (uint32_t)(bt * 16) * 128u + brb;
            uint32_t B0, B1, B2, B3;
            LDSM_X4(B0, B1, B2, B3, smb + OFF_W + brow_off);
            MMA16816(&D[(2 * bt) * 4],     A0, A1, A2, A3, B0, B1);
            MMA16816(&D[(2 * bt + 1) * 4], A0, A1, A2, A3, B2, B3);
        }
    }

    __syncwarp();

    float pa = 0.0f, pb = 0.0f;

    // ---- epilogue: gates, h update (hold from smem), fp16 store ----
    #pragma unroll
    for (int t = 0; t < 8; ++t) {
        const int g2 = t * 8 + tg * 2;
        float2 war = *(const float2*)(cf + CF_WA + g2);
        float2 waz = *(const float2*)(cf + CF_WA + 64 + g2);
        float2 wan = *(const float2*)(cf + CF_WA + 128 + g2);
        float2 brr = *(const float2*)(cf + CF_BRZ + g2);
        float2 brz = *(const float2*)(cf + CF_BRZ + 64 + g2);
        float2 bin = *(const float2*)(cf + CF_BIHN + g2);
        float2 bhn = *(const float2*)(cf + CF_BHHN + g2);
        float2 wbr, wbz, wbn;
        if (HASX1) {
            wbr = *(const float2*)(cf + CF_WB + g2);
            wbz = *(const float2*)(cf + CF_WB + 64 + g2);
            wbn = *(const float2*)(cf + CF_WB + 128 + g2);
        }
        float2 l1;
        if (WANTV) l1 = *(const float2*)(cf + CF_L1W + g2);

        #pragma unroll
        for (int rh = 0; rh < 2; ++rh) {
            const float x0 = rh ? xb0 : xa0;
            const float x1 = rh ? xb1 : xa1;
            const uint32_t off = (uint32_t)(warp * 16 + group + rh * 8) * 128u
                               + (uint32_t)(((t ^ group) << 4) + tg * 4);
            __half2 hold2 = *(__half2*)(smem + OFF_A + off);
            float2 holdf = __half22float2(hold2);
            float hn[2];
            #pragma unroll
            for (int u = 0; u < 2; ++u) {
                float pr = D[t * 4 + rh * 2 + u]        + (u ? brr.y : brr.x) + (u ? war.y : war.x) * x0;
                float pz = D[(t + 8) * 4 + rh * 2 + u]  + (u ? brz.y : brz.x) + (u ? waz.y : waz.x) * x0;
                float pn = D[(t + 16) * 4 + rh * 2 + u] + (u ? bhn.y : bhn.x);
                float gx = (u ? bin.y : bin.x) + (u ? wan.y : wan.x) * x0;
                if (HASX1) {
                    pr = fmaf((u ? wbr.y : wbr.x), x1, pr);
                    pz = fmaf((u ? wbz.y : wbz.x), x1, pz);
                    gx = fmaf((u ? wbn.y : wbn.x), x1, gx);
                }
                float rr = sigmoid_fast(pr);
                float zz = sigmoid_fast(pz);
                float nn = tanh_fast(fmaf(rr, pn, gx));
                float hold = u ? holdf.y : holdf.x;
                hn[u] = nn + zz * (hold - nn);
            }
            *(__half2*)(smem + OFF_A + off) = __floats2half2_rn(hn[0], hn[1]);
            if (WANTV) {
                float d = fmaf(hn[0], l1.x, hn[1] * l1.y);
                if (rh == 0) pa += d; else pb += d;
            }
        }
    }
    if (WANTV) { va_out = pa; vb_out = pb; }
}

// ===================== main kernel =====================
__global__ void __launch_bounds__(NT, 2) krnn_mma(
    const float* __restrict__ X,
    const float* __restrict__ enc_w_ih, const float* __restrict__ enc_w_hh,
    const float* __restrict__ enc_b_ih, const float* __restrict__ enc_b_hh,
    const float* __restrict__ dec_w_ih, const float* __restrict__ dec_w_hh,
    const float* __restrict__ dec_b_ih, const float* __restrict__ dec_b_hh,
    const float* __restrict__ lin1_w,   const float* __restrict__ lin1_b)
{
    extern __shared__ unsigned char smem[];
    const int tid   = threadIdx.x;
    const int l     = tid & 31;
    const int warp  = tid >> 5;
    const int c     = (CC - 1) - blockIdx.y;          // longest-first
    const uint32_t smb = smem_u32_of(smem);

    const int group = l >> 2;
    const int tg    = l & 3;
    const int arow  = (l & 7) + ((l >> 3) & 1) * 8;
    const int acoff = (l >> 4) & 1;
    const int brow  = (l & 7) + ((l >> 4) & 1) * 8;
    const int bcoff = (l >> 3) & 1;
    const int sw7   = l & 7;

    const int seq_a = blockIdx.x * SEQ_PER_CTA + warp * 16 + group;
    const int seq_b = seq_a + 8;

    // stage ENCODER weights; zero A tile (h = 0)
    stage_w(smem, tid, enc_w_hh + c * (G3 * HH), enc_w_ih + c * (G3 * 2), 2,
            enc_b_ih + c * G3, enc_b_hh + c * G3, lin1_w + c * HH, lin1_b + c);
    {
        uint4 z; z.x = z.y = z.z = z.w = 0u;
        for (int i = tid * 16; i < 16384; i += NT * 16)
            *(uint4*)(smem + OFF_A + i) = z;
    }
    __syncthreads();

    const float* cf = (const float*)(smem + OFF_COEF);
    float vdum0, vdum1;

    // ---- encoder ----
    const int s_enc = c + 3;
    const float2* hvp = (const float2*)g_hv;
    #pragma unroll 1
    for (int st = 0; st < s_enc; ++st) {
        float2 xa = hvp[(size_t)(c * TOUT + st) * BN + seq_a];
        float2 xb = hvp[(size_t)(c * TOUT + st) * BN + seq_b];
        mma_step<true, false>(smem, smb, cf, warp, group, tg,
                              arow, acoff, brow, bcoff, sw7,
                              xa.x, xa.y, xb.x, xb.y, vdum0, vdum1);
    }

    // ---- restage DECODER weights ----
    __syncthreads();
    stage_w(smem, tid, dec_w_hh + c * (G3 * HH), dec_w_ih + c * G3, 1,
            dec_b_ih + c * G3, dec_b_hh + c * G3, lin1_w + c * HH, lin1_b + c);
    __syncthreads();

    const float l1b = cf[CF_L1B];

    float va = X[(size_t)seq_a * (TT * 2) + 22];      // X[seq, t=11, f=0]
    float vb = X[(size_t)seq_b * (TT * 2) + 22];

    // ---- decoder ----
    #pragma unroll 1
    for (int st = 0; st < TOUT; ++st) {
        float pa, pb;
        mma_step<false, true>(smem, smb, cf, warp, group, tg,
                              arow, acoff, brow, bcoff, sw7,
                              va, 0.0f, vb, 0.0f, pa, pb);
        pa += __shfl_xor_sync(0xffffffff, pa, 1);
        pa += __shfl_xor_sync(0xffffffff, pa, 2);
        pb += __shfl_xor_sync(0xffffffff, pb, 1);
        pb += __shfl_xor_sync(0xffffffff, pb, 2);
        va = pa + l1b;
        vb = pb + l1b;
        if (tg == 0) {
            g_vals[(size_t)(c * TOUT + st) * BN + seq_a] = va;
            g_vals[(size_t)(c * TOUT + st) * BN + seq_b] = vb;
        }
    }
}

// ===================== hv precompute =====================
__global__ void __launch_bounds__(256) krnn_hv(
    const float* __restrict__ X,
    const float* __restrict__ lin2_w, const float* __restrict__ lin2_b)
{
    const int seq = blockIdx.x * 256 + threadIdx.x;
    float Xl[24];
    {
        const float4* xp = (const float4*)(X + (size_t)seq * (TT * 2));
        #pragma unroll
        for (int q = 0; q < 6; ++q) {
            float4 v = xp[q];
            Xl[4*q+0] = v.x; Xl[4*q+1] = v.y; Xl[4*q+2] = v.z; Xl[4*q+3] = v.w;
        }
    }
    float2* hvp = (float2*)g_hv;
    for (int c = 0; c < CC; ++c) {
        const int s = c + 3;
        for (int st = 0; st < s; ++st) {
            float b = lin2_b[c * 12 + st];
            float x0 = b, x1 = b;
            #pragma unroll
            for (int t = 0; t < TT; ++t) {
                float w = lin2_w[c * 144 + st * 12 + t];
                x0 = fmaf(Xl[2 * t],     w, x0);
                x1 = fmaf(Xl[2 * t + 1], w, x1);
            }
            hvp[(size_t)(c * TOUT + st) * BN + seq] = make_float2(x0, x1);
        }
    }
}

// ===================== final combine =====================
__global__ void __launch_bounds__(256) krnn_combine(
    const float* __restrict__ X,
    const float* __restrict__ embed1,
    float* __restrict__ out)
{
    const int seq = blockIdx.x * 256 + threadIdx.x;

    float q[TT];
    #pragma unroll
    for (int t = 0; t < TT; ++t) q[t] = X[(size_t)seq * (TT * 2) + t * 2];

    float wq[TOUT];
    #pragma unroll
    for (int o = 0; o < TOUT; ++o) {
        float a = 0.0f;
        #pragma unroll
        for (int t = 0; t < TT; ++t) a = fmaf(q[t], embed1[t * TOUT + o], a);
        wq[o] = a;
    }

    float ov[TOUT * CC];
    #pragma unroll
    for (int cc = 0; cc < CC; ++cc)
        #pragma unroll
        for (int o = 0; o < TOUT; ++o)
            ov[o * CC + cc] = g_vals[((size_t)cc * TOUT + o) * BN + seq];

    float wc[CC];
    #pragma unroll
    for (int cc = 0; cc < CC; ++cc) {
        float a = 0.0f;
        #pragma unroll
        for (int o = 0; o < TOUT; ++o) a = fmaf(wq[o], ov[o * CC + cc], a);
        wc[cc] = a;
    }

    float m = wc[0];
    #pragma unroll
    for (int cc = 1; cc < CC; ++cc) m = fmaxf(m, wc[cc]);
    float e[CC]; float ssum = 0.0f;
    #pragma unroll
    for (int cc = 0; cc < CC; ++cc) { e[cc] = expf(wc[cc] - m); ssum += e[cc]; }
    float inv = 1.0f / ssum;

    #pragma unroll
    for (int o = 0; o < TOUT; ++o) {
        float a = 0.0f;
        #pragma unroll
        for (int cc = 0; cc < CC; ++cc) a = fmaf(ov[o * CC + cc], e[cc], a);
        out[(size_t)seq * TOUT + o] = a * inv;
    }
}

extern "C" void kernel_launch(void* const* d_in, const int* in_sizes, int n_in,
                              void* d_out, int out_size)
{
    const float* X        = (const float*)d_in[1];
    const float* enc_w_ih = (const float*)d_in[2];
    const float* enc_w_hh = (const float*)d_in[3];
    const float* enc_b_ih = (const float*)d_in[4];
    const float* enc_b_hh = (const float*)d_in[5];
    const float* dec_w_ih = (const float*)d_in[6];
    const float* dec_w_hh = (const float*)d_in[7];
    const float* dec_b_ih = (const float*)d_in[8];
    const float* dec_b_hh = (const float*)d_in[9];
    const float* lin1_w   = (const float*)d_in[10];
    const float* lin1_b   = (const float*)d_in[11];
    const float* lin2_w   = (const float*)d_in[12];
    const float* lin2_b   = (const float*)d_in[13];
    const float* embed1   = (const float*)d_in[14];

    cudaFuncSetAttribute(krnn_mma, cudaFuncAttributeMaxDynamicSharedMemorySize, SMEM_BYTES);

    krnn_hv<<<BN / 256, 256>>>(X, lin2_w, lin2_b);

    dim3 grid(BN / SEQ_PER_CTA, CC);
    krnn_mma<<<grid, NT, SMEM_BYTES>>>(
        X, enc_w_ih, enc_w_hh, enc_b_ih, enc_b_hh,
        dec_w_ih, dec_w_hh, dec_b_ih, dec_b_hh,
        lin1_w, lin1_b);

    krnn_combine<<<BN / 256, 256>>>(X, embed1, (float*)d_out);
}

// round 12
// speedup vs baseline: 6.0757x; 1.0546x over previous
#include <cuda_runtime.h>
#include <cuda_fp16.h>
#include <cstdint>

// Problem constants
#define BN    131072
#define TT    12
#define HH    64
#define G3    192
#define CC    10
#define TOUT  12
#define NT    256            // 8 warps; warp = 16 seqs; CTA tile = 128 seqs
#define SEQ_PER_CTA 128
#define NITER 4              // seq-tiles per CTA (persistent staging)

// ---- SMEM byte offsets ----
#define OFF_A    0                 // h fp16: 128 rows x 128B, swizzled (per-warp-private 16-row bands)
#define OFF_WE   16384             // enc W fp16: 192 rows x 128B, swizzled
#define OFF_WD   40960             // dec W fp16
#define OFF_CFE  65536             // enc float coef block (708 floats)
#define OFF_CFD  68368             // dec float coef block
#define SMEM_BYTES (OFF_CFD + 708*4)
// coef float indices
#define CF_WA   0                  // w_ih feature0 [192]
#define CF_WB   192                // w_ih feature1 [192]
#define CF_BRZ  384                // b_ih+b_hh for r,z [128]
#define CF_BIHN 512                // b_ih n [64]
#define CF_BHHN 576                // b_hh n [64]
#define CF_L1W  640                // lin1 weights [64]
#define CF_L1B  704                // lin1 bias [1]

// device-global scratch
__device__ float g_hv[(size_t)CC * TOUT * BN * 2];   // encoder inputs (x0,x1)
__device__ float g_vals[(size_t)CC * TOUT * BN];     // decoder outputs

// ===================== helpers =====================
__device__ __forceinline__ uint32_t smem_u32_of(const void* p) {
    uint32_t a;
    asm("{ .reg .u64 t; cvta.to.shared.u64 t, %1; cvt.u32.u64 %0, t; }" : "=r"(a) : "l"(p));
    return a;
}
__device__ __forceinline__ float sigmoid_fast(float x) {
    float t, y = 0.5f * x;
    asm("tanh.approx.f32 %0, %1;" : "=f"(t) : "f"(y));
    return fmaf(0.5f, t, 0.5f);
}
__device__ __forceinline__ float tanh_fast(float x) {
    float t;
    asm("tanh.approx.f32 %0, %1;" : "=f"(t) : "f"(x));
    return t;
}

#define LDSM_X4(r0, r1, r2, r3, addr) \
    asm volatile("ldmatrix.sync.aligned.m8n8.x4.shared.b16 {%0,%1,%2,%3}, [%4];" \
                 : "=r"(r0), "=r"(r1), "=r"(r2), "=r"(r3) : "r"(addr))

#define MMA16816(dp, a0, a1, a2, a3, b0, b1) \
    asm volatile("mma.sync.aligned.m16n8k16.row.col.f32.f16.f16.f32 " \
                 "{%0,%1,%2,%3}, {%4,%5,%6,%7}, {%8,%9}, {%0,%1,%2,%3};" \
                 : "+f"((dp)[0]), "+f"((dp)[1]), "+f"((dp)[2]), "+f"((dp)[3]) \
                 : "r"(a0), "r"(a1), "r"(a2), "r"(a3), "r"(b0), "r"(b1))

// ===================== weight staging =====================
__device__ __forceinline__ void stage_w(
    unsigned char* smem, int tid, uint32_t wofs, uint32_t cfofs,
    const float* __restrict__ whh, const float* __restrict__ wih, int stride,
    const float* __restrict__ bih, const float* __restrict__ bhh,
    const float* __restrict__ l1w, const float* __restrict__ l1b)
{
    for (int idx = tid; idx < G3 * HH; idx += NT) {
        int g = idx >> 6, k = idx & 63;
        __half hi = __float2half_rn(whh[idx]);
        uint32_t off = (uint32_t)g * 128u + (uint32_t)((((k >> 3) ^ (g & 7)) << 4) + (k & 7) * 2);
        *(__half*)(smem + wofs + off) = hi;
    }
    float* cf = (float*)(smem + cfofs);
    for (int t = tid; t < G3; t += NT) {
        cf[CF_WA + t] = wih[t * stride];
        cf[CF_WB + t] = (stride == 2) ? wih[t * 2 + 1] : 0.0f;
        float bi = bih[t], bh = bhh[t];
        if (t < 128) cf[CF_BRZ + t] = bi + bh;
        else { cf[CF_BIHN + t - 128] = bi; cf[CF_BHHN + t - 128] = bh; }
    }
    if (tid < HH)  cf[CF_L1W + tid] = l1w[tid];
    if (tid == HH) cf[CF_L1B] = l1b[0];
}

// ===================== one GRU step (mma.sync, fp16, h in smem only) ===========
// D = W·h, W and h fp16. Old h read back from the A tile (value this thread
// stored last step). A tile rows are per-warp-private -> only __syncwarp needed.
// WANTV: fuse the lin1 dot (fp32) into the epilogue; pa/pb partial dots returned.
template<bool HASX1, bool WANTV>
__device__ __forceinline__ void mma_step(
    unsigned char* smem, uint32_t smb, uint32_t wofs, const float* cf,
    int warp, int group, int tg,
    int arow, int acoff, int brow, int bcoff, int sw7,
    float xa0, float xa1, float xb0, float xb1,
    float& va_out, float& vb_out)
{
    float D[96];
    #pragma unroll
    for (int i = 0; i < 96; ++i) D[i] = 0.0f;

    __syncwarp();

    const uint32_t a_row_b = (uint32_t)(warp * 16 + arow) * 128u;
    const uint32_t wbase = smb + wofs;

    #pragma unroll 1
    for (int kcb = 0; kcb < 4; ++kcb) {
        const int kc = kcb * 2;

        uint32_t A0, A1, A2, A3;
        uint32_t aaddr = smb + OFF_A + a_row_b + (uint32_t)(((kc + acoff) ^ sw7) << 4);
        LDSM_X4(A0, A1, A2, A3, aaddr);

        const uint32_t bsw = (uint32_t)(((kc + bcoff) ^ sw7) << 4);
        const uint32_t brb = (uint32_t)brow * 128u + bsw;
        #pragma unroll
        for (int bt = 0; bt < 12; ++bt) {
            const uint32_t brow_off = (uint32_t)(bt * 16) * 128u + brb;
            uint32_t B0, B1, B2, B3;
            LDSM_X4(B0, B1, B2, B3, wbase + brow_off);
            MMA16816(&D[(2 * bt) * 4],     A0, A1, A2, A3, B0, B1);
            MMA16816(&D[(2 * bt + 1) * 4], A0, A1, A2, A3, B2, B3);
        }
    }

    __syncwarp();

    float pa = 0.0f, pb = 0.0f;

    // ---- epilogue: gates, h update (hold from smem), fp16 store ----
    #pragma unroll
    for (int t = 0; t < 8; ++t) {
        const int g2 = t * 8 + tg * 2;
        float2 war = *(const float2*)(cf + CF_WA + g2);
        float2 waz = *(const float2*)(cf + CF_WA + 64 + g2);
        float2 wan = *(const float2*)(cf + CF_WA + 128 + g2);
        float2 brr = *(const float2*)(cf + CF_BRZ + g2);
        float2 brz = *(const float2*)(cf + CF_BRZ + 64 + g2);
        float2 bin = *(const float2*)(cf + CF_BIHN + g2);
        float2 bhn = *(const float2*)(cf + CF_BHHN + g2);
        float2 wbr, wbz, wbn;
        if (HASX1) {
            wbr = *(const float2*)(cf + CF_WB + g2);
            wbz = *(const float2*)(cf + CF_WB + 64 + g2);
            wbn = *(const float2*)(cf + CF_WB + 128 + g2);
        }
        float2 l1;
        if (WANTV) l1 = *(const float2*)(cf + CF_L1W + g2);

        #pragma unroll
        for (int rh = 0; rh < 2; ++rh) {
            const float x0 = rh ? xb0 : xa0;
            const float x1 = rh ? xb1 : xa1;
            const uint32_t off = (uint32_t)(warp * 16 + group + rh * 8) * 128u
                               + (uint32_t)(((t ^ group) << 4) + tg * 4);
            __half2 hold2 = *(__half2*)(smem + OFF_A + off);
            float2 holdf = __half22float2(hold2);
            float hn[2];
            #pragma unroll
            for (int u = 0; u < 2; ++u) {
                float pr = D[t * 4 + rh * 2 + u]        + (u ? brr.y : brr.x) + (u ? war.y : war.x) * x0;
                float pz = D[(t + 8) * 4 + rh * 2 + u]  + (u ? brz.y : brz.x) + (u ? waz.y : waz.x) * x0;
                float pn = D[(t + 16) * 4 + rh * 2 + u] + (u ? bhn.y : bhn.x);
                float gx = (u ? bin.y : bin.x) + (u ? wan.y : wan.x) * x0;
                if (HASX1) {
                    pr = fmaf((u ? wbr.y : wbr.x), x1, pr);
                    pz = fmaf((u ? wbz.y : wbz.x), x1, pz);
                    gx = fmaf((u ? wbn.y : wbn.x), x1, gx);
                }
                float rr = sigmoid_fast(pr);
                float zz = sigmoid_fast(pz);
                float nn = tanh_fast(fmaf(rr, pn, gx));
                float hold = u ? holdf.y : holdf.x;
                hn[u] = nn + zz * (hold - nn);
            }
            *(__half2*)(smem + OFF_A + off) = __floats2half2_rn(hn[0], hn[1]);
            if (WANTV) {
                float d = fmaf(hn[0], l1.x, hn[1] * l1.y);
                if (rh == 0) pa += d; else pb += d;
            }
        }
    }
    if (WANTV) { va_out = pa; vb_out = pb; }
}

// ===================== main kernel =====================
__global__ void __launch_bounds__(NT, 2) krnn_mma(
    const float* __restrict__ X,
    const float* __restrict__ enc_w_ih, const float* __restrict__ enc_w_hh,
    const float* __restrict__ enc_b_ih, const float* __restrict__ enc_b_hh,
    const float* __restrict__ dec_w_ih, const float* __restrict__ dec_w_hh,
    const float* __restrict__ dec_b_ih, const float* __restrict__ dec_b_hh,
    const float* __restrict__ lin1_w,   const float* __restrict__ lin1_b)
{
    extern __shared__ unsigned char smem[];
    const int tid   = threadIdx.x;
    const int l     = tid & 31;
    const int warp  = tid >> 5;
    const int c     = (CC - 1) - blockIdx.y;          // longest-first
    const uint32_t smb = smem_u32_of(smem);

    const int group = l >> 2;
    const int tg    = l & 3;
    const int arow  = (l & 7) + ((l >> 3) & 1) * 8;
    const int acoff = (l >> 4) & 1;
    const int brow  = (l & 7) + ((l >> 4) & 1) * 8;
    const int bcoff = (l >> 3) & 1;
    const int sw7   = l & 7;

    // stage BOTH weight sets once per CTA
    stage_w(smem, tid, OFF_WE, OFF_CFE,
            enc_w_hh + c * (G3 * HH), enc_w_ih + c * (G3 * 2), 2,
            enc_b_ih + c * G3, enc_b_hh + c * G3, lin1_w + c * HH, lin1_b + c);
    stage_w(smem, tid, OFF_WD, OFF_CFD,
            dec_w_hh + c * (G3 * HH), dec_w_ih + c * G3, 1,
            dec_b_ih + c * G3, dec_b_hh + c * G3, lin1_w + c * HH, lin1_b + c);
    __syncthreads();          // the ONLY block-wide barrier

    const float* cfe = (const float*)(smem + OFF_CFE);
    const float* cfd = (const float*)(smem + OFF_CFD);
    const float  l1b = cfd[CF_L1B];
    const int    s_enc = c + 3;
    const float2* hvc = (const float2*)g_hv + (size_t)c * TOUT * BN;
    float vdum0, vdum1;

    #pragma unroll 1
    for (int tile = 0; tile < NITER; ++tile) {
        const int seq_a = (blockIdx.x * NITER + tile) * SEQ_PER_CTA + warp * 16 + group;
        const int seq_b = seq_a + 8;

        // zero this warp's private A rows (h = 0); mma_step's syncwarp orders it
        {
            uint4 z; z.x = z.y = z.z = z.w = 0u;
            const uint32_t abase = (uint32_t)warp * 2048u;
            #pragma unroll
            for (int i = 0; i < 4; ++i)
                *(uint4*)(smem + OFF_A + abase + (uint32_t)(l * 16 + i * 512)) = z;
        }

        // ---- encoder ----
        #pragma unroll 1
        for (int st = 0; st < s_enc; ++st) {
            float2 xa = hvc[(size_t)st * BN + seq_a];
            float2 xb = hvc[(size_t)st * BN + seq_b];
            mma_step<true, false>(smem, smb, OFF_WE, cfe, warp, group, tg,
                                  arow, acoff, brow, bcoff, sw7,
                                  xa.x, xa.y, xb.x, xb.y, vdum0, vdum1);
        }

        // ---- decoder ----
        float va = X[(size_t)seq_a * (TT * 2) + 22];      // X[seq, t=11, f=0]
        float vb = X[(size_t)seq_b * (TT * 2) + 22];
        #pragma unroll 1
        for (int st = 0; st < TOUT; ++st) {
            float pa, pb;
            mma_step<false, true>(smem, smb, OFF_WD, cfd, warp, group, tg,
                                  arow, acoff, brow, bcoff, sw7,
                                  va, 0.0f, vb, 0.0f, pa, pb);
            pa += __shfl_xor_sync(0xffffffff, pa, 1);
            pa += __shfl_xor_sync(0xffffffff, pa, 2);
            pb += __shfl_xor_sync(0xffffffff, pb, 1);
            pb += __shfl_xor_sync(0xffffffff, pb, 2);
            va = pa + l1b;
            vb = pb + l1b;
            if (tg == 0) {
                g_vals[(size_t)(c * TOUT + st) * BN + seq_a] = va;
                g_vals[(size_t)(c * TOUT + st) * BN + seq_b] = vb;
            }
        }
    }
}

// ===================== hv precompute =====================
__global__ void __launch_bounds__(256) krnn_hv(
    const float* __restrict__ X,
    const float* __restrict__ lin2_w, const float* __restrict__ lin2_b)
{
    const int seq = blockIdx.x * 256 + threadIdx.x;
    float Xl[24];
    {
        const float4* xp = (const float4*)(X + (size_t)seq * (TT * 2));
        #pragma unroll
        for (int q = 0; q < 6; ++q) {
            float4 v = xp[q];
            Xl[4*q+0] = v.x; Xl[4*q+1] = v.y; Xl[4*q+2] = v.z; Xl[4*q+3] = v.w;
        }
    }
    float2* hvp = (float2*)g_hv;
    for (int c = 0; c < CC; ++c) {
        const int s = c + 3;
        for (int st = 0; st < s; ++st) {
            float b = lin2_b[c * 12 + st];
            float x0 = b, x1 = b;
            #pragma unroll
            for (int t = 0; t < TT; ++t) {
                float w = lin2_w[c * 144 + st * 12 + t];
                x0 = fmaf(Xl[2 * t],     w, x0);
                x1 = fmaf(Xl[2 * t + 1], w, x1);
            }
            hvp[(size_t)(c * TOUT + st) * BN + seq] = make_float2(x0, x1);
        }
    }
}

// ===================== final combine =====================
__global__ void __launch_bounds__(256) krnn_combine(
    const float* __restrict__ X,
    const float* __restrict__ embed1,
    float* __restrict__ out)
{
    const int seq = blockIdx.x * 256 + threadIdx.x;

    float q[TT];
    #pragma unroll
    for (int t = 0; t < TT; ++t) q[t] = X[(size_t)seq * (TT * 2) + t * 2];

    float wq[TOUT];
    #pragma unroll
    for (int o = 0; o < TOUT; ++o) {
        float a = 0.0f;
        #pragma unroll
        for (int t = 0; t < TT; ++t) a = fmaf(q[t], embed1[t * TOUT + o], a);
        wq[o] = a;
    }

    float ov[TOUT * CC];
    #pragma unroll
    for (int cc = 0; cc < CC; ++cc)
        #pragma unroll
        for (int o = 0; o < TOUT; ++o)
            ov[o * CC + cc] = g_vals[((size_t)cc * TOUT + o) * BN + seq];

    float wc[CC];
    #pragma unroll
    for (int cc = 0; cc < CC; ++cc) {
        float a = 0.0f;
        #pragma unroll
        for (int o = 0; o < TOUT; ++o) a = fmaf(wq[o], ov[o * CC + cc], a);
        wc[cc] = a;
    }

    float m = wc[0];
    #pragma unroll
    for (int cc = 1; cc < CC; ++cc) m = fmaxf(m, wc[cc]);
    float e[CC]; float ssum = 0.0f;
    #pragma unroll
    for (int cc = 0; cc < CC; ++cc) { e[cc] = expf(wc[cc] - m); ssum += e[cc]; }
    float inv = 1.0f / ssum;

    #pragma unroll
    for (int o = 0; o < TOUT; ++o) {
        float a = 0.0f;
        #pragma unroll
        for (int cc = 0; cc < CC; ++cc) a = fmaf(ov[o * CC + cc], e[cc], a);
        out[(size_t)seq * TOUT + o] = a * inv;
    }
}

extern "C" void kernel_launch(void* const* d_in, const int* in_sizes, int n_in,
                              void* d_out, int out_size)
{
    const float* X        = (const float*)d_in[1];
    const float* enc_w_ih = (const float*)d_in[2];
    const float* enc_w_hh = (const float*)d_in[3];
    const float* enc_b_ih = (const float*)d_in[4];
    const float* enc_b_hh = (const float*)d_in[5];
    const float* dec_w_ih = (const float*)d_in[6];
    const float* dec_w_hh = (const float*)d_in[7];
    const float* dec_b_ih = (const float*)d_in[8];
    const float* dec_b_hh = (const float*)d_in[9];
    const float* lin1_w   = (const float*)d_in[10];
    const float* lin1_b   = (const float*)d_in[11];
    const float* lin2_w   = (const float*)d_in[12];
    const float* lin2_b   = (const float*)d_in[13];
    const float* embed1   = (const float*)d_in[14];

    cudaFuncSetAttribute(krnn_mma, cudaFuncAttributeMaxDynamicSharedMemorySize, SMEM_BYTES);

    krnn_hv<<<BN / 256, 256>>>(X, lin2_w, lin2_b);

    dim3 grid(BN / (SEQ_PER_CTA * NITER), CC);
    krnn_mma<<<grid, NT, SMEM_BYTES>>>(
        X, enc_w_ih, enc_w_hh, enc_b_ih, enc_b_hh,
        dec_w_ih, dec_w_hh, dec_b_ih, dec_b_hh,
        lin1_w, lin1_b);

    krnn_combine<<<BN / 256, 256>>>(X, embed1, (float*)d_out);
}

// round 13
// speedup vs baseline: 6.2429x; 1.0275x over previous
#include <cuda_runtime.h>
#include <cuda_fp16.h>
#include <cstdint>

// Problem constants
#define BN    131072
#define TT    12
#define HH    64
#define G3    192
#define CC    10
#define TOUT  12
#define NT    256            // 8 warps; warp = 16 seqs; CTA tile = 128 seqs
#define SEQ_PER_CTA 128
#define NITER 4              // seq-tiles per CTA (persistent staging)

// ---- SMEM byte offsets ----
#define OFF_A    0                 // h fp16: 128 rows x 128B, swizzled (per-warp-private 16-row bands)
#define OFF_WE   16384             // enc W fp16: 192 rows x 128B, swizzled
#define OFF_WD   40960             // dec W fp16
#define OFF_CFE  65536             // enc float coef block (708 floats)
#define OFF_CFD  68368             // dec float coef block
#define SMEM_BYTES (OFF_CFD + 708*4)
// coef float indices
#define CF_WA   0                  // w_ih feature0 [192]
#define CF_WB   192                // w_ih feature1 [192]
#define CF_BRZ  384                // b_ih+b_hh for r,z [128]
#define CF_BIHN 512                // b_ih n [64]
#define CF_BHHN 576                // b_hh n [64]
#define CF_L1W  640                // lin1 weights [64]
#define CF_L1B  704                // lin1 bias [1]

// device-global scratch
__device__ float g_hv[(size_t)CC * TOUT * BN * 2];   // encoder inputs (x0,x1)
__device__ float g_vals[(size_t)CC * TOUT * BN];     // decoder outputs

// ===================== helpers =====================
__device__ __forceinline__ uint32_t smem_u32_of(const void* p) {
    uint32_t a;
    asm("{ .reg .u64 t; cvta.to.shared.u64 t, %1; cvt.u32.u64 %0, t; }" : "=r"(a) : "l"(p));
    return a;
}
__device__ __forceinline__ float sigmoid_fast(float x) {
    float t, y = 0.5f * x;
    asm("tanh.approx.f32 %0, %1;" : "=f"(t) : "f"(y));
    return fmaf(0.5f, t, 0.5f);
}
__device__ __forceinline__ float tanh_fast(float x) {
    float t;
    asm("tanh.approx.f32 %0, %1;" : "=f"(t) : "f"(x));
    return t;
}

#define LDSM_X4(r0, r1, r2, r3, addr) \
    asm volatile("ldmatrix.sync.aligned.m8n8.x4.shared.b16 {%0,%1,%2,%3}, [%4];" \
                 : "=r"(r0), "=r"(r1), "=r"(r2), "=r"(r3) : "r"(addr))

// fp16-accumulate HMMA: D/C fragment = 2 x f16x2 regs (rh0 pair, rh1 pair)
#define MMA16816H(dp, a0, a1, a2, a3, b0, b1) \
    asm volatile("mma.sync.aligned.m16n8k16.row.col.f16.f16.f16.f16 " \
                 "{%0,%1}, {%2,%3,%4,%5}, {%6,%7}, {%0,%1};" \
                 : "+r"((dp)[0]), "+r"((dp)[1]) \
                 : "r"(a0), "r"(a1), "r"(a2), "r"(a3), "r"(b0), "r"(b1))

// ===================== weight staging =====================
__device__ __forceinline__ void stage_w(
    unsigned char* smem, int tid, uint32_t wofs, uint32_t cfofs,
    const float* __restrict__ whh, const float* __restrict__ wih, int stride,
    const float* __restrict__ bih, const float* __restrict__ bhh,
    const float* __restrict__ l1w, const float* __restrict__ l1b)
{
    for (int idx = tid; idx < G3 * HH; idx += NT) {
        int g = idx >> 6, k = idx & 63;
        __half hi = __float2half_rn(whh[idx]);
        uint32_t off = (uint32_t)g * 128u + (uint32_t)((((k >> 3) ^ (g & 7)) << 4) + (k & 7) * 2);
        *(__half*)(smem + wofs + off) = hi;
    }
    float* cf = (float*)(smem + cfofs);
    for (int t = tid; t < G3; t += NT) {
        cf[CF_WA + t] = wih[t * stride];
        cf[CF_WB + t] = (stride == 2) ? wih[t * 2 + 1] : 0.0f;
        float bi = bih[t], bh = bhh[t];
        if (t < 128) cf[CF_BRZ + t] = bi + bh;
        else { cf[CF_BIHN + t - 128] = bi; cf[CF_BHHN + t - 128] = bh; }
    }
    if (tid < HH)  cf[CF_L1W + tid] = l1w[tid];
    if (tid == HH) cf[CF_L1B] = l1b[0];
}

// ===================== one GRU step (mma.sync fp16-accum, h in smem) ===========
// D (fp16 accum) = W·h. Dh[T*2+rh] is an f16x2 holding the (u=0,u=1) pair of
// n-tile T, row-group rh. Epilogue unpacks to fp32; gate math unchanged.
template<bool HASX1, bool WANTV>
__device__ __forceinline__ void mma_step(
    unsigned char* smem, uint32_t smb, uint32_t wofs, const float* cf,
    int warp, int group, int tg,
    int arow, int acoff, int brow, int bcoff, int sw7,
    float xa0, float xa1, float xb0, float xb1,
    float& va_out, float& vb_out)
{
    uint32_t Dh[48];
    #pragma unroll
    for (int i = 0; i < 48; ++i) Dh[i] = 0u;

    __syncwarp();

    const uint32_t a_row_b = (uint32_t)(warp * 16 + arow) * 128u;
    const uint32_t wbase = smb + wofs;

    #pragma unroll 1
    for (int kcb = 0; kcb < 4; ++kcb) {
        const int kc = kcb * 2;

        uint32_t A0, A1, A2, A3;
        uint32_t aaddr = smb + OFF_A + a_row_b + (uint32_t)(((kc + acoff) ^ sw7) << 4);
        LDSM_X4(A0, A1, A2, A3, aaddr);

        const uint32_t bsw = (uint32_t)(((kc + bcoff) ^ sw7) << 4);
        const uint32_t brb = (uint32_t)brow * 128u + bsw;
        #pragma unroll
        for (int bt = 0; bt < 12; ++bt) {
            const uint32_t brow_off = (uint32_t)(bt * 16) * 128u + brb;
            uint32_t B0, B1, B2, B3;
            LDSM_X4(B0, B1, B2, B3, wbase + brow_off);
            MMA16816H(&Dh[4 * bt],     A0, A1, A2, A3, B0, B1);
            MMA16816H(&Dh[4 * bt + 2], A0, A1, A2, A3, B2, B3);
        }
    }

    __syncwarp();

    float pa = 0.0f, pb = 0.0f;

    // ---- epilogue: gates (fp32), h update (hold from smem), fp16 store ----
    #pragma unroll
    for (int t = 0; t < 8; ++t) {
        const int g2 = t * 8 + tg * 2;
        float2 war = *(const float2*)(cf + CF_WA + g2);
        float2 waz = *(const float2*)(cf + CF_WA + 64 + g2);
        float2 wan = *(const float2*)(cf + CF_WA + 128 + g2);
        float2 brr = *(const float2*)(cf + CF_BRZ + g2);
        float2 brz = *(const float2*)(cf + CF_BRZ + 64 + g2);
        float2 bin = *(const float2*)(cf + CF_BIHN + g2);
        float2 bhn = *(const float2*)(cf + CF_BHHN + g2);
        float2 wbr, wbz, wbn;
        if (HASX1) {
            wbr = *(const float2*)(cf + CF_WB + g2);
            wbz = *(const float2*)(cf + CF_WB + 64 + g2);
            wbn = *(const float2*)(cf + CF_WB + 128 + g2);
        }
        float2 l1;
        if (WANTV) l1 = *(const float2*)(cf + CF_L1W + g2);

        #pragma unroll
        for (int rh = 0; rh < 2; ++rh) {
            const float x0 = rh ? xb0 : xa0;
            const float x1 = rh ? xb1 : xa1;
            const uint32_t off = (uint32_t)(warp * 16 + group + rh * 8) * 128u
                               + (uint32_t)(((t ^ group) << 4) + tg * 4);
            __half2 hold2 = *(__half2*)(smem + OFF_A + off);
            float2 holdf = __half22float2(hold2);
            // unpack fp16-accumulated gate pre-activations
            float2 dr = __half22float2(*(__half2*)&Dh[t * 2 + rh]);
            float2 dz = __half22float2(*(__half2*)&Dh[(t + 8) * 2 + rh]);
            float2 dn = __half22float2(*(__half2*)&Dh[(t + 16) * 2 + rh]);
            float hn[2];
            #pragma unroll
            for (int u = 0; u < 2; ++u) {
                float pr = (u ? dr.y : dr.x) + (u ? brr.y : brr.x) + (u ? war.y : war.x) * x0;
                float pz = (u ? dz.y : dz.x) + (u ? brz.y : brz.x) + (u ? waz.y : waz.x) * x0;
                float pn = (u ? dn.y : dn.x) + (u ? bhn.y : bhn.x);
                float gx = (u ? bin.y : bin.x) + (u ? wan.y : wan.x) * x0;
                if (HASX1) {
                    pr = fmaf((u ? wbr.y : wbr.x), x1, pr);
                    pz = fmaf((u ? wbz.y : wbz.x), x1, pz);
                    gx = fmaf((u ? wbn.y : wbn.x), x1, gx);
                }
                float rr = sigmoid_fast(pr);
                float zz = sigmoid_fast(pz);
                float nn = tanh_fast(fmaf(rr, pn, gx));
                float hold = u ? holdf.y : holdf.x;
                hn[u] = nn + zz * (hold - nn);
            }
            *(__half2*)(smem + OFF_A + off) = __floats2half2_rn(hn[0], hn[1]);
            if (WANTV) {
                float d = fmaf(hn[0], l1.x, hn[1] * l1.y);
                if (rh == 0) pa += d; else pb += d;
            }
        }
    }
    if (WANTV) { va_out = pa; vb_out = pb; }
}

// ===================== main kernel =====================
__global__ void __launch_bounds__(NT, 2) krnn_mma(
    const float* __restrict__ X,
    const float* __restrict__ enc_w_ih, const float* __restrict__ enc_w_hh,
    const float* __restrict__ enc_b_ih, const float* __restrict__ enc_b_hh,
    const float* __restrict__ dec_w_ih, const float* __restrict__ dec_w_hh,
    const float* __restrict__ dec_b_ih, const float* __restrict__ dec_b_hh,
    const float* __restrict__ lin1_w,   const float* __restrict__ lin1_b)
{
    extern __shared__ unsigned char smem[];
    const int tid   = threadIdx.x;
    const int l     = tid & 31;
    const int warp  = tid >> 5;
    const int c     = (CC - 1) - blockIdx.y;          // longest-first
    const uint32_t smb = smem_u32_of(smem);

    const int group = l >> 2;
    const int tg    = l & 3;
    const int arow  = (l & 7) + ((l >> 3) & 1) * 8;
    const int acoff = (l >> 4) & 1;
    const int brow  = (l & 7) + ((l >> 4) & 1) * 8;
    const int bcoff = (l >> 3) & 1;
    const int sw7   = l & 7;

    // stage BOTH weight sets once per CTA
    stage_w(smem, tid, OFF_WE, OFF_CFE,
            enc_w_hh + c * (G3 * HH), enc_w_ih + c * (G3 * 2), 2,
            enc_b_ih + c * G3, enc_b_hh + c * G3, lin1_w + c * HH, lin1_b + c);
    stage_w(smem, tid, OFF_WD, OFF_CFD,
            dec_w_hh + c * (G3 * HH), dec_w_ih + c * G3, 1,
            dec_b_ih + c * G3, dec_b_hh + c * G3, lin1_w + c * HH, lin1_b + c);
    __syncthreads();          // the ONLY block-wide barrier

    const float* cfe = (const float*)(smem + OFF_CFE);
    const float* cfd = (const float*)(smem + OFF_CFD);
    const float  l1b = cfd[CF_L1B];
    const int    s_enc = c + 3;
    const float2* hvc = (const float2*)g_hv + (size_t)c * TOUT * BN;
    float vdum0, vdum1;

    #pragma unroll 1
    for (int tile = 0; tile < NITER; ++tile) {
        const int seq_a = (blockIdx.x * NITER + tile) * SEQ_PER_CTA + warp * 16 + group;
        const int seq_b = seq_a + 8;

        // zero this warp's private A rows (h = 0); mma_step's syncwarp orders it
        {
            uint4 z; z.x = z.y = z.z = z.w = 0u;
            const uint32_t abase = (uint32_t)warp * 2048u;
            #pragma unroll
            for (int i = 0; i < 4; ++i)
                *(uint4*)(smem + OFF_A + abase + (uint32_t)(l * 16 + i * 512)) = z;
        }

        // ---- encoder ----
        #pragma unroll 1
        for (int st = 0; st < s_enc; ++st) {
            float2 xa = hvc[(size_t)st * BN + seq_a];
            float2 xb = hvc[(size_t)st * BN + seq_b];
            mma_step<true, false>(smem, smb, OFF_WE, cfe, warp, group, tg,
                                  arow, acoff, brow, bcoff, sw7,
                                  xa.x, xa.y, xb.x, xb.y, vdum0, vdum1);
        }

        // ---- decoder ----
        float va = X[(size_t)seq_a * (TT * 2) + 22];      // X[seq, t=11, f=0]
        float vb = X[(size_t)seq_b * (TT * 2) + 22];
        #pragma unroll 1
        for (int st = 0; st < TOUT; ++st) {
            float pa, pb;
            mma_step<false, true>(smem, smb, OFF_WD, cfd, warp, group, tg,
                                  arow, acoff, brow, bcoff, sw7,
                                  va, 0.0f, vb, 0.0f, pa, pb);
            pa += __shfl_xor_sync(0xffffffff, pa, 1);
            pa += __shfl_xor_sync(0xffffffff, pa, 2);
            pb += __shfl_xor_sync(0xffffffff, pb, 1);
            pb += __shfl_xor_sync(0xffffffff, pb, 2);
            va = pa + l1b;
            vb = pb + l1b;
            if (tg == 0) {
                g_vals[(size_t)(c * TOUT + st) * BN + seq_a] = va;
                g_vals[(size_t)(c * TOUT + st) * BN + seq_b] = vb;
            }
        }
    }
}

// ===================== hv precompute =====================
__global__ void __launch_bounds__(256) krnn_hv(
    const float* __restrict__ X,
    const float* __restrict__ lin2_w, const float* __restrict__ lin2_b)
{
    const int seq = blockIdx.x * 256 + threadIdx.x;
    float Xl[24];
    {
        const float4* xp = (const float4*)(X + (size_t)seq * (TT * 2));
        #pragma unroll
        for (int q = 0; q < 6; ++q) {
            float4 v = xp[q];
            Xl[4*q+0] = v.x; Xl[4*q+1] = v.y; Xl[4*q+2] = v.z; Xl[4*q+3] = v.w;
        }
    }
    float2* hvp = (float2*)g_hv;
    for (int c = 0; c < CC; ++c) {
        const int s = c + 3;
        for (int st = 0; st < s; ++st) {
            float b = lin2_b[c * 12 + st];
            float x0 = b, x1 = b;
            #pragma unroll
            for (int t = 0; t < TT; ++t) {
                float w = lin2_w[c * 144 + st * 12 + t];
                x0 = fmaf(Xl[2 * t],     w, x0);
                x1 = fmaf(Xl[2 * t + 1], w, x1);
            }
            hvp[(size_t)(c * TOUT + st) * BN + seq] = make_float2(x0, x1);
        }
    }
}

// ===================== final combine =====================
__global__ void __launch_bounds__(256) krnn_combine(
    const float* __restrict__ X,
    const float* __restrict__ embed1,
    float* __restrict__ out)
{
    const int seq = blockIdx.x * 256 + threadIdx.x;

    float q[TT];
    #pragma unroll
    for (int t = 0; t < TT; ++t) q[t] = X[(size_t)seq * (TT * 2) + t * 2];

    float wq[TOUT];
    #pragma unroll
    for (int o = 0; o < TOUT; ++o) {
        float a = 0.0f;
        #pragma unroll
        for (int t = 0; t < TT; ++t) a = fmaf(q[t], embed1[t * TOUT + o], a);
        wq[o] = a;
    }

    float ov[TOUT * CC];
    #pragma unroll
    for (int cc = 0; cc < CC; ++cc)
        #pragma unroll
        for (int o = 0; o < TOUT; ++o)
            ov[o * CC + cc] = g_vals[((size_t)cc * TOUT + o) * BN + seq];

    float wc[CC];
    #pragma unroll
    for (int cc = 0; cc < CC; ++cc) {
        float a = 0.0f;
        #pragma unroll
        for (int o = 0; o < TOUT; ++o) a = fmaf(wq[o], ov[o * CC + cc], a);
        wc[cc] = a;
    }

    float m = wc[0];
    #pragma unroll
    for (int cc = 1; cc < CC; ++cc) m = fmaxf(m, wc[cc]);
    float e[CC]; float ssum = 0.0f;
    #pragma unroll
    for (int cc = 0; cc < CC; ++cc) { e[cc] = expf(wc[cc] - m); ssum += e[cc]; }
    float inv = 1.0f / ssum;

    #pragma unroll
    for (int o = 0; o < TOUT; ++o) {
        float a = 0.0f;
        #pragma unroll
        for (int cc = 0; cc < CC; ++cc) a = fmaf(ov[o * CC + cc], e[cc], a);
        out[(size_t)seq * TOUT + o] = a * inv;
    }
}

extern "C" void kernel_launch(void* const* d_in, const int* in_sizes, int n_in,
                              void* d_out, int out_size)
{
    const float* X        = (const float*)d_in[1];
    const float* enc_w_ih = (const float*)d_in[2];
    const float* enc_w_hh = (const float*)d_in[3];
    const float* enc_b_ih = (const float*)d_in[4];
    const float* enc_b_hh = (const float*)d_in[5];
    const float* dec_w_ih = (const float*)d_in[6];
    const float* dec_w_hh = (const float*)d_in[7];
    const float* dec_b_ih = (const float*)d_in[8];
    const float* dec_b_hh = (const float*)d_in[9];
    const float* lin1_w   = (const float*)d_in[10];
    const float* lin1_b   = (const float*)d_in[11];
    const float* lin2_w   = (const float*)d_in[12];
    const float* lin2_b   = (const float*)d_in[13];
    const float* embed1   = (const float*)d_in[14];

    cudaFuncSetAttribute(krnn_mma, cudaFuncAttributeMaxDynamicSharedMemorySize, SMEM_BYTES);

    krnn_hv<<<BN / 256, 256>>>(X, lin2_w, lin2_b);

    dim3 grid(BN / (SEQ_PER_CTA * NITER), CC);
    krnn_mma<<<grid, NT, SMEM_BYTES>>>(
        X, enc_w_ih, enc_w_hh, enc_b_ih, enc_b_hh,
        dec_w_ih, dec_w_hh, dec_b_ih, dec_b_hh,
        lin1_w, lin1_b);

    krnn_combine<<<BN / 256, 256>>>(X, embed1, (float*)d_out);
}